// round 1
// baseline (speedup 1.0000x reference)
#include <cuda_runtime.h>
#include <math.h>

// Problem constants
#define BB 4
#define TT 2048
#define INF_ 64
#define DD 512
#define HH 8
#define DH 64
#define FF_ 2048
#define LL 4
#define LAT 128
#define PAST 40
#define FUT 120
#define ROWS (BB*TT)          // 8192
#define EPS 1e-5f

// ---------------- scratch (device globals; no allocation allowed) ----------
__device__ float g_x   [ROWS * DD];        // 16 MB
__device__ float g_qkv [ROWS * 3 * DD];    // 48 MB
__device__ float g_ctx [ROWS * DD];        // 16 MB
__device__ float g_tmp [ROWS * DD];        // 16 MB
__device__ float g_ff  [ROWS * FF_];       // 64 MB
__device__ float g_pool[BB * DD];
__device__ float g_h   [BB * 2 * LAT];

// ---------------- SGEMM: C[M,N] = A[M,K] @ B[K,N] (+bias, epilogue) --------
// EPI: 0 = +bias ; 1 = +bias, relu ; 2 = +bias + pos_enc[row%T]
template <int EPI>
__global__ __launch_bounds__(256)
void sgemm128(const float* __restrict__ A, const float* __restrict__ B,
              const float* __restrict__ bias, const float* __restrict__ extra,
              float* __restrict__ C, int M, int N, int K)
{
    constexpr int BM = 128, BN = 128, BK = 8, TM = 8, TN = 8;
    __shared__ float As[BK][BM];
    __shared__ float Bs[BK][BN];

    const int tid  = threadIdx.x;        // 0..255
    const int tx   = tid & 15;           // 16 cols of threads
    const int ty   = tid >> 4;           // 16 rows of threads
    const int brow = blockIdx.y;
    const int bcol = blockIdx.x;

    // A tile load: 128 rows x 8 cols = 256 float4 (2 per row)
    const int a_row = tid >> 1;
    const int a_col = (tid & 1) * 4;
    // B tile load: 8 rows x 128 cols = 256 float4
    const int b_row = tid >> 5;
    const int b_col = (tid & 31) * 4;

    const float* Ap = A + (size_t)(brow * BM) * K;
    const float* Bp = B + bcol * BN;

    float acc[TM][TN];
#pragma unroll
    for (int i = 0; i < TM; i++)
#pragma unroll
        for (int j = 0; j < TN; j++) acc[i][j] = 0.f;

    for (int k0 = 0; k0 < K; k0 += BK) {
        float4 av = *(const float4*)(Ap + (size_t)a_row * K + k0 + a_col);
        As[a_col + 0][a_row] = av.x;
        As[a_col + 1][a_row] = av.y;
        As[a_col + 2][a_row] = av.z;
        As[a_col + 3][a_row] = av.w;
        float4 bv = *(const float4*)(Bp + (size_t)(k0 + b_row) * N + b_col);
        *(float4*)&Bs[b_row][b_col] = bv;
        __syncthreads();

#pragma unroll
        for (int k = 0; k < BK; k++) {
            float ar[TM], br[TN];
            float4 a0 = *(const float4*)&As[k][ty * TM];
            float4 a1 = *(const float4*)&As[k][ty * TM + 4];
            ar[0]=a0.x; ar[1]=a0.y; ar[2]=a0.z; ar[3]=a0.w;
            ar[4]=a1.x; ar[5]=a1.y; ar[6]=a1.z; ar[7]=a1.w;
            float4 b0 = *(const float4*)&Bs[k][tx * TN];
            float4 b1 = *(const float4*)&Bs[k][tx * TN + 4];
            br[0]=b0.x; br[1]=b0.y; br[2]=b0.z; br[3]=b0.w;
            br[4]=b1.x; br[5]=b1.y; br[6]=b1.z; br[7]=b1.w;
#pragma unroll
            for (int i = 0; i < TM; i++)
#pragma unroll
                for (int j = 0; j < TN; j++)
                    acc[i][j] = fmaf(ar[i], br[j], acc[i][j]);
        }
        __syncthreads();
    }

#pragma unroll
    for (int i = 0; i < TM; i++) {
        int row = brow * BM + ty * TM + i;
#pragma unroll
        for (int jj = 0; jj < TN; jj += 4) {
            int col = bcol * BN + tx * TN + jj;
            float4 v;
            v.x = acc[i][jj+0] + bias[col+0];
            v.y = acc[i][jj+1] + bias[col+1];
            v.z = acc[i][jj+2] + bias[col+2];
            v.w = acc[i][jj+3] + bias[col+3];
            if (EPI == 1) {
                v.x = fmaxf(v.x, 0.f); v.y = fmaxf(v.y, 0.f);
                v.z = fmaxf(v.z, 0.f); v.w = fmaxf(v.w, 0.f);
            }
            if (EPI == 2) {
                int t = row & (TT - 1);
                const float4 pe = *(const float4*)(extra + (size_t)t * N + col);
                v.x += pe.x; v.y += pe.y; v.z += pe.z; v.w += pe.w;
            }
            *(float4*)(C + (size_t)row * N + col) = v;
        }
    }
}

// ---------------- banded attention: warp per query, online softmax ---------
__global__ __launch_bounds__(256)
void banded_attn(const float* __restrict__ qkv, float* __restrict__ ctx)
{
    const int w    = blockIdx.x * 8 + (threadIdx.x >> 5);   // global warp = query id
    const int lane = threadIdx.x & 31;
    if (w >= BB * HH * TT) return;
    const int b = w / (HH * TT);
    const int h = (w / TT) % HH;
    const int t = w % TT;

    const float scale = 0.125f;  // 1/sqrt(64)
    const float* qb = qkv + ((size_t)(b * TT + t)) * (3 * DD) + h * DH;
    const float q0 = qb[lane], q1 = qb[lane + 32];

    const int lo = max(0, t - PAST);
    const int hi = min(TT - 1, t + FUT);

    float m = -INFINITY, l = 0.f, acc0 = 0.f, acc1 = 0.f;
    for (int j = lo; j <= hi; j++) {
        const float* kb = qkv + ((size_t)(b * TT + j)) * (3 * DD) + DD + h * DH;
        const float* vb = kb + DD;  // v is DD after k
        float part = q0 * kb[lane] + q1 * kb[lane + 32];
#pragma unroll
        for (int off = 16; off > 0; off >>= 1)
            part += __shfl_xor_sync(0xffffffffu, part, off);
        const float s = part * scale;
        const float mnew = fmaxf(m, s);
        const float c = __expf(m - mnew);
        const float p = __expf(s - mnew);
        l    = l * c + p;
        acc0 = acc0 * c + p * vb[lane];
        acc1 = acc1 * c + p * vb[lane + 32];
        m = mnew;
    }
    const float inv = 1.f / l;
    float* ob = ctx + ((size_t)(b * TT + t)) * DD + h * DH;
    ob[lane]      = acc0 * inv;
    ob[lane + 32] = acc1 * inv;
}

// ---------------- residual add + LayerNorm (row = 512) ---------------------
__global__ __launch_bounds__(128)
void add_ln(const float* __restrict__ x, const float* __restrict__ y,
            const float* __restrict__ s, const float* __restrict__ bta,
            float* __restrict__ out)
{
    const int row = blockIdx.x;
    const int tid = threadIdx.x;      // 128 threads, 4 elems each
    float v[4];
    float sum = 0.f, sq = 0.f;
#pragma unroll
    for (int i = 0; i < 4; i++) {
        int c = tid + i * 128;
        float val = x[(size_t)row * DD + c] + y[(size_t)row * DD + c];
        v[i] = val;
        sum += val;
        sq  += val * val;
    }
    // block reduce (4 warps)
    __shared__ float rs[8];
#pragma unroll
    for (int off = 16; off > 0; off >>= 1) {
        sum += __shfl_xor_sync(0xffffffffu, sum, off);
        sq  += __shfl_xor_sync(0xffffffffu, sq,  off);
    }
    if ((tid & 31) == 0) { rs[tid >> 5] = sum; rs[4 + (tid >> 5)] = sq; }
    __syncthreads();
    sum = rs[0] + rs[1] + rs[2] + rs[3];
    sq  = rs[4] + rs[5] + rs[6] + rs[7];
    const float mean = sum * (1.f / DD);
    const float var  = sq * (1.f / DD) - mean * mean;
    const float inv  = rsqrtf(var + EPS);
#pragma unroll
    for (int i = 0; i < 4; i++) {
        int c = tid + i * 128;
        out[(size_t)row * DD + c] = (v[i] - mean) * inv * s[c] + bta[c];
    }
}

// ---------------- mean pool over T -----------------------------------------
__global__ void mean_pool(const float* __restrict__ emb, float* __restrict__ p)
{
    const int b = blockIdx.x, d = threadIdx.x;   // 512 threads
    float sum = 0.f;
    for (int t = 0; t < TT; t++)
        sum += emb[((size_t)(b * TT + t)) * DD + d];
    p[b * DD + d] = sum * (1.f / TT);
}

// ---------------- tiny dense layer (heads) ----------------------------------
__global__ void small_linear(const float* __restrict__ in, const float* __restrict__ W,
                             const float* __restrict__ bias, float* __restrict__ out,
                             int K, int N, int relu)
{
    const int b = blockIdx.x, n = threadIdx.x;
    if (n >= N) return;
    float sum = bias[n];
    for (int k = 0; k < K; k++)
        sum = fmaf(in[b * K + k], W[(size_t)k * N + n], sum);
    if (relu) sum = fmaxf(sum, 0.f);
    out[b * N + n] = sum;
}

// ---------------- launch -----------------------------------------------------
extern "C" void kernel_launch(void* const* d_in, const int* in_sizes, int n_in,
                              void* d_out, int out_size)
{
    const float* feats  = (const float*)d_in[0];
    const float* projW  = (const float*)d_in[1];
    const float* projB  = (const float*)d_in[2];
    const float* posenc = (const float*)d_in[3];
    const float* qkvW   = (const float*)d_in[4];
    const float* qkvB   = (const float*)d_in[5];
    const float* outW   = (const float*)d_in[6];
    const float* outB   = (const float*)d_in[7];
    const float* ln1s   = (const float*)d_in[8];
    const float* ln1b   = (const float*)d_in[9];
    const float* ff1W   = (const float*)d_in[10];
    const float* ff1B   = (const float*)d_in[11];
    const float* ff2W   = (const float*)d_in[12];
    const float* ff2B   = (const float*)d_in[13];
    const float* ln2s   = (const float*)d_in[14];
    const float* ln2b   = (const float*)d_in[15];
    const float* mu1W   = (const float*)d_in[16];
    const float* mu1B   = (const float*)d_in[17];
    const float* mu2W   = (const float*)d_in[18];
    const float* mu2B   = (const float*)d_in[19];
    const float* lv1W   = (const float*)d_in[20];
    const float* lv1B   = (const float*)d_in[21];
    const float* lv2W   = (const float*)d_in[22];
    const float* lv2B   = (const float*)d_in[23];

    float *px, *pqkv, *pctx, *ptmp, *pff, *ppool, *ph;
    cudaGetSymbolAddress((void**)&px,    g_x);
    cudaGetSymbolAddress((void**)&pqkv,  g_qkv);
    cudaGetSymbolAddress((void**)&pctx,  g_ctx);
    cudaGetSymbolAddress((void**)&ptmp,  g_tmp);
    cudaGetSymbolAddress((void**)&pff,   g_ff);
    cudaGetSymbolAddress((void**)&ppool, g_pool);
    cudaGetSymbolAddress((void**)&ph,    g_h);

    float* emb = (float*)d_out;                       // [8192, 512]
    float* mu  = emb + (size_t)ROWS * DD;             // [4, 128]
    float* lv  = mu + BB * LAT;

    // x = feats @ projW + projB + posenc
    {
        dim3 grid(DD / 128, ROWS / 128);
        sgemm128<2><<<grid, 256>>>(feats, projW, projB, posenc, px, ROWS, DD, INF_);
    }

    for (int l = 0; l < LL; l++) {
        // qkv = x @ qkvW[l] + qkvB[l]
        {
            dim3 grid((3 * DD) / 128, ROWS / 128);
            sgemm128<0><<<grid, 256>>>(px, qkvW + (size_t)l * DD * 3 * DD,
                                       qkvB + l * 3 * DD, nullptr, pqkv,
                                       ROWS, 3 * DD, DD);
        }
        // banded attention
        banded_attn<<<(BB * HH * TT) / 8, 256>>>(pqkv, pctx);
        // out proj
        {
            dim3 grid(DD / 128, ROWS / 128);
            sgemm128<0><<<grid, 256>>>(pctx, outW + (size_t)l * DD * DD,
                                       outB + l * DD, nullptr, ptmp, ROWS, DD, DD);
        }
        add_ln<<<ROWS, 128>>>(px, ptmp, ln1s + l * DD, ln1b + l * DD, px);
        // ff1 (relu)
        {
            dim3 grid(FF_ / 128, ROWS / 128);
            sgemm128<1><<<grid, 256>>>(px, ff1W + (size_t)l * DD * FF_,
                                       ff1B + l * FF_, nullptr, pff, ROWS, FF_, DD);
        }
        // ff2
        {
            dim3 grid(DD / 128, ROWS / 128);
            sgemm128<0><<<grid, 256>>>(pff, ff2W + (size_t)l * FF_ * DD,
                                       ff2B + l * DD, nullptr, ptmp, ROWS, DD, FF_);
        }
        float* dst = (l == LL - 1) ? emb : px;
        add_ln<<<ROWS, 128>>>(px, ptmp, ln2s + l * DD, ln2b + l * DD, dst);
    }

    // pooled mean + heads
    mean_pool<<<BB, DD>>>(emb, ppool);
    small_linear<<<BB, 2 * LAT>>>(ppool, mu1W, mu1B, ph, DD, 2 * LAT, 1);
    small_linear<<<BB, LAT>>>(ph, mu2W, mu2B, mu, 2 * LAT, LAT, 0);
    small_linear<<<BB, 2 * LAT>>>(ppool, lv1W, lv1B, ph, DD, 2 * LAT, 1);
    small_linear<<<BB, LAT>>>(ph, lv2W, lv2B, lv, 2 * LAT, LAT, 0);
}

// round 2
// speedup vs baseline: 1.7757x; 1.7757x over previous
#include <cuda_runtime.h>
#include <math.h>
#include <stdint.h>

// Problem constants
#define BB 4
#define TT 2048
#define INF_ 64
#define DD 512
#define HH 8
#define DH 64
#define FF_ 2048
#define LL 4
#define LAT 128
#define PAST 40
#define FUT 120
#define ROWS (BB*TT)          // 8192
#define EPS 1e-5f

// ---------------- scratch (device globals; no allocation allowed) ----------
__device__ float g_x   [ROWS * DD];
__device__ float g_qkv [ROWS * 3 * DD];
__device__ float g_ctx [ROWS * DD];
__device__ float g_tmp [ROWS * DD];
__device__ float g_ff  [ROWS * FF_];
__device__ float g_pool[BB * DD];
__device__ float g_pp  [BB * 32 * DD];
__device__ float g_h   [BB * 2 * LAT];

// ---------------- helpers ---------------------------------------------------
__device__ __forceinline__ float f2tf(float x) {
    uint32_t u;
    asm("cvt.rna.tf32.f32 %0, %1;" : "=r"(u) : "f"(x));
    return __uint_as_float(u);
}

#define MMA_TF32(d0,d1,d2,d3,a0,a1,a2,a3,b0,b1)                              \
    asm volatile("mma.sync.aligned.m16n8k8.row.col.f32.tf32.tf32.f32 "       \
        "{%0,%1,%2,%3},{%4,%5,%6,%7},{%8,%9},{%0,%1,%2,%3};"                 \
        : "+f"(d0),"+f"(d1),"+f"(d2),"+f"(d3)                                \
        : "r"(a0),"r"(a1),"r"(a2),"r"(a3),"r"(b0),"r"(b1))

// ---------------- TF32 tensor-core GEMM: C = A[M,K] @ B[K,N] + bias ---------
// EPI: 0 = +bias ; 1 = +bias, relu ; 2 = +bias + pos_enc[row%T]
template <int EPI>
__global__ __launch_bounds__(256)
void gemm_tf32(const float* __restrict__ A, const float* __restrict__ B,
               const float* __restrict__ bias, const float* __restrict__ extra,
               float* __restrict__ C, int M, int N, int K)
{
    constexpr int BM = 128, BN = 128, BK = 16;
    __shared__ float As[2][BM][BK + 4];   // [m][k], pad 4 -> conflict-free frag reads
    __shared__ float Bs[2][BK][BN + 4];   // [k][n], pad 4

    const int tid  = threadIdx.x;
    const int wid  = tid >> 5, lane = tid & 31;
    const int g    = lane >> 2, c = lane & 3;
    const int wm   = (wid >> 2) * 64;     // 2 warp-rows
    const int wn   = (wid & 3) * 32;      // 4 warp-cols
    const int brow = blockIdx.y * BM, bcol = blockIdx.x * BN;

    // global-load mapping
    const int arow = tid >> 1,  acol  = (tid & 1) * 8;    // A: 2 thr/row, 8 floats each
    const int brw  = tid >> 4,  bcl   = (tid & 15) * 8;   // B: 16 thr/row, 8 floats each

    const float* Ag = A + (size_t)(brow + arow) * K + acol;
    const float* Bg = B + (size_t)brw * N + bcol + bcl;

    float4 pa0, pa1, pb0, pb1;
    pa0 = *(const float4*)(Ag);
    pa1 = *(const float4*)(Ag + 4);
    pb0 = *(const float4*)(Bg);
    pb1 = *(const float4*)(Bg + 4);

    float acc[4][4][4];
#pragma unroll
    for (int i = 0; i < 4; i++)
#pragma unroll
        for (int j = 0; j < 4; j++)
#pragma unroll
            for (int r = 0; r < 4; r++) acc[i][j][r] = 0.f;

    // store tile 0
    {
        float* pA = &As[0][arow][acol];
        pA[0]=f2tf(pa0.x); pA[1]=f2tf(pa0.y); pA[2]=f2tf(pa0.z); pA[3]=f2tf(pa0.w);
        pA[4]=f2tf(pa1.x); pA[5]=f2tf(pa1.y); pA[6]=f2tf(pa1.z); pA[7]=f2tf(pa1.w);
        float* pB = &Bs[0][brw][bcl];
        pB[0]=f2tf(pb0.x); pB[1]=f2tf(pb0.y); pB[2]=f2tf(pb0.z); pB[3]=f2tf(pb0.w);
        pB[4]=f2tf(pb1.x); pB[5]=f2tf(pb1.y); pB[6]=f2tf(pb1.z); pB[7]=f2tf(pb1.w);
    }
    __syncthreads();

    const int nk = K / BK;
    int buf = 0;
    for (int k0 = 0; k0 < nk; k0++) {
        // prefetch next tile from global
        if (k0 + 1 < nk) {
            const float* Agn = Ag + (k0 + 1) * BK;
            const float* Bgn = Bg + (size_t)(k0 + 1) * BK * N;
            pa0 = *(const float4*)(Agn);
            pa1 = *(const float4*)(Agn + 4);
            pb0 = *(const float4*)(Bgn);
            pb1 = *(const float4*)(Bgn + 4);
        }

        // compute on current buffer
#pragma unroll
        for (int kk = 0; kk < 2; kk++) {
            uint32_t af[4][4];
#pragma unroll
            for (int mt = 0; mt < 4; mt++) {
                const int m0 = wm + mt * 16 + g;
                af[mt][0] = __float_as_uint(As[buf][m0    ][kk*8 + c    ]);
                af[mt][1] = __float_as_uint(As[buf][m0 + 8][kk*8 + c    ]);
                af[mt][2] = __float_as_uint(As[buf][m0    ][kk*8 + c + 4]);
                af[mt][3] = __float_as_uint(As[buf][m0 + 8][kk*8 + c + 4]);
            }
            uint32_t bf[4][2];
#pragma unroll
            for (int nt = 0; nt < 4; nt++) {
                const int n0 = wn + nt * 8 + g;
                bf[nt][0] = __float_as_uint(Bs[buf][kk*8 + c    ][n0]);
                bf[nt][1] = __float_as_uint(Bs[buf][kk*8 + c + 4][n0]);
            }
#pragma unroll
            for (int mt = 0; mt < 4; mt++)
#pragma unroll
                for (int nt = 0; nt < 4; nt++)
                    MMA_TF32(acc[mt][nt][0], acc[mt][nt][1], acc[mt][nt][2], acc[mt][nt][3],
                             af[mt][0], af[mt][1], af[mt][2], af[mt][3],
                             bf[nt][0], bf[nt][1]);
        }

        // store prefetched tile into the other buffer
        if (k0 + 1 < nk) {
            const int nb = buf ^ 1;
            float* pA = &As[nb][arow][acol];
            pA[0]=f2tf(pa0.x); pA[1]=f2tf(pa0.y); pA[2]=f2tf(pa0.z); pA[3]=f2tf(pa0.w);
            pA[4]=f2tf(pa1.x); pA[5]=f2tf(pa1.y); pA[6]=f2tf(pa1.z); pA[7]=f2tf(pa1.w);
            float* pB = &Bs[nb][brw][bcl];
            pB[0]=f2tf(pb0.x); pB[1]=f2tf(pb0.y); pB[2]=f2tf(pb0.z); pB[3]=f2tf(pb0.w);
            pB[4]=f2tf(pb1.x); pB[5]=f2tf(pb1.y); pB[6]=f2tf(pb1.z); pB[7]=f2tf(pb1.w);
            __syncthreads();
            buf = nb;
        }
    }

    // epilogue: acc frag (row g / g+8, col 2c / 2c+1)
#pragma unroll
    for (int mt = 0; mt < 4; mt++) {
#pragma unroll
        for (int nt = 0; nt < 4; nt++) {
            const int col = bcol + wn + nt * 8 + 2 * c;
            const float b0 = bias[col], b1 = bias[col + 1];
#pragma unroll
            for (int half = 0; half < 2; half++) {
                const int row = brow + wm + mt * 16 + g + half * 8;
                float v0 = acc[mt][nt][half * 2 + 0] + b0;
                float v1 = acc[mt][nt][half * 2 + 1] + b1;
                if (EPI == 1) { v0 = fmaxf(v0, 0.f); v1 = fmaxf(v1, 0.f); }
                if (EPI == 2) {
                    const int t = row & (TT - 1);
                    v0 += extra[(size_t)t * N + col];
                    v1 += extra[(size_t)t * N + col + 1];
                }
                float2 o; o.x = v0; o.y = v1;
                *(float2*)(C + (size_t)row * N + col) = o;
            }
        }
    }
}

// ---------------- banded attention: warp per query, online softmax ---------
__global__ __launch_bounds__(256)
void banded_attn(const float* __restrict__ qkv, float* __restrict__ ctx)
{
    const int w    = blockIdx.x * 8 + (threadIdx.x >> 5);
    const int lane = threadIdx.x & 31;
    if (w >= BB * HH * TT) return;
    const int b = w / (HH * TT);
    const int h = (w / TT) % HH;
    const int t = w % TT;

    const float scale = 0.125f;
    const float* qb = qkv + ((size_t)(b * TT + t)) * (3 * DD) + h * DH;
    const float q0 = qb[lane], q1 = qb[lane + 32];

    const int lo = max(0, t - PAST);
    const int hi = min(TT - 1, t + FUT);

    float m = -INFINITY, l = 0.f, acc0 = 0.f, acc1 = 0.f;
    for (int j = lo; j <= hi; j++) {
        const float* kb = qkv + ((size_t)(b * TT + j)) * (3 * DD) + DD + h * DH;
        const float* vb = kb + DD;
        float part = q0 * kb[lane] + q1 * kb[lane + 32];
#pragma unroll
        for (int off = 16; off > 0; off >>= 1)
            part += __shfl_xor_sync(0xffffffffu, part, off);
        const float s = part * scale;
        const float mnew = fmaxf(m, s);
        const float cc = __expf(m - mnew);
        const float p = __expf(s - mnew);
        l    = l * cc + p;
        acc0 = acc0 * cc + p * vb[lane];
        acc1 = acc1 * cc + p * vb[lane + 32];
        m = mnew;
    }
    const float inv = 1.f / l;
    float* ob = ctx + ((size_t)(b * TT + t)) * DD + h * DH;
    ob[lane]      = acc0 * inv;
    ob[lane + 32] = acc1 * inv;
}

// ---------------- residual add + LayerNorm (row = 512) ---------------------
__global__ __launch_bounds__(128)
void add_ln(const float* __restrict__ x, const float* __restrict__ y,
            const float* __restrict__ s, const float* __restrict__ bta,
            float* __restrict__ out)
{
    const int row = blockIdx.x;
    const int tid = threadIdx.x;
    float v[4];
    float sum = 0.f, sq = 0.f;
#pragma unroll
    for (int i = 0; i < 4; i++) {
        int c = tid + i * 128;
        float val = x[(size_t)row * DD + c] + y[(size_t)row * DD + c];
        v[i] = val;
        sum += val;
        sq  += val * val;
    }
    __shared__ float rs[8];
#pragma unroll
    for (int off = 16; off > 0; off >>= 1) {
        sum += __shfl_xor_sync(0xffffffffu, sum, off);
        sq  += __shfl_xor_sync(0xffffffffu, sq,  off);
    }
    if ((tid & 31) == 0) { rs[tid >> 5] = sum; rs[4 + (tid >> 5)] = sq; }
    __syncthreads();
    sum = rs[0] + rs[1] + rs[2] + rs[3];
    sq  = rs[4] + rs[5] + rs[6] + rs[7];
    const float mean = sum * (1.f / DD);
    const float var  = sq * (1.f / DD) - mean * mean;
    const float inv  = rsqrtf(var + EPS);
#pragma unroll
    for (int i = 0; i < 4; i++) {
        int c = tid + i * 128;
        out[(size_t)row * DD + c] = (v[i] - mean) * inv * s[c] + bta[c];
    }
}

// ---------------- mean pool (two-stage) -------------------------------------
__global__ void pool_partial(const float* __restrict__ emb, float* __restrict__ pp)
{
    const int b = blockIdx.x >> 5, ch = blockIdx.x & 31;
    const int d = threadIdx.x;
    float s = 0.f;
    const int t0 = ch * 64;
    for (int t = t0; t < t0 + 64; t++)
        s += emb[((size_t)(b * TT + t)) * DD + d];
    pp[(size_t)blockIdx.x * DD + d] = s;
}

__global__ void pool_reduce(const float* __restrict__ pp, float* __restrict__ p)
{
    const int b = blockIdx.x, d = threadIdx.x;
    float s = 0.f;
    for (int ch = 0; ch < 32; ch++)
        s += pp[(size_t)(b * 32 + ch) * DD + d];
    p[b * DD + d] = s * (1.f / TT);
}

// ---------------- tiny dense layer (heads) ----------------------------------
__global__ void small_linear(const float* __restrict__ in, const float* __restrict__ W,
                             const float* __restrict__ bias, float* __restrict__ out,
                             int K, int N, int relu)
{
    const int b = blockIdx.x, n = threadIdx.x;
    if (n >= N) return;
    float sum = bias[n];
    for (int k = 0; k < K; k++)
        sum = fmaf(in[b * K + k], W[(size_t)k * N + n], sum);
    if (relu) sum = fmaxf(sum, 0.f);
    out[b * N + n] = sum;
}

// ---------------- launch -----------------------------------------------------
extern "C" void kernel_launch(void* const* d_in, const int* in_sizes, int n_in,
                              void* d_out, int out_size)
{
    const float* feats  = (const float*)d_in[0];
    const float* projW  = (const float*)d_in[1];
    const float* projB  = (const float*)d_in[2];
    const float* posenc = (const float*)d_in[3];
    const float* qkvW   = (const float*)d_in[4];
    const float* qkvB   = (const float*)d_in[5];
    const float* outW   = (const float*)d_in[6];
    const float* outB   = (const float*)d_in[7];
    const float* ln1s   = (const float*)d_in[8];
    const float* ln1b   = (const float*)d_in[9];
    const float* ff1W   = (const float*)d_in[10];
    const float* ff1B   = (const float*)d_in[11];
    const float* ff2W   = (const float*)d_in[12];
    const float* ff2B   = (const float*)d_in[13];
    const float* ln2s   = (const float*)d_in[14];
    const float* ln2b   = (const float*)d_in[15];
    const float* mu1W   = (const float*)d_in[16];
    const float* mu1B   = (const float*)d_in[17];
    const float* mu2W   = (const float*)d_in[18];
    const float* mu2B   = (const float*)d_in[19];
    const float* lv1W   = (const float*)d_in[20];
    const float* lv1B   = (const float*)d_in[21];
    const float* lv2W   = (const float*)d_in[22];
    const float* lv2B   = (const float*)d_in[23];

    float *px, *pqkv, *pctx, *ptmp, *pff, *ppool, *ppp, *ph;
    cudaGetSymbolAddress((void**)&px,    g_x);
    cudaGetSymbolAddress((void**)&pqkv,  g_qkv);
    cudaGetSymbolAddress((void**)&pctx,  g_ctx);
    cudaGetSymbolAddress((void**)&ptmp,  g_tmp);
    cudaGetSymbolAddress((void**)&pff,   g_ff);
    cudaGetSymbolAddress((void**)&ppool, g_pool);
    cudaGetSymbolAddress((void**)&ppp,   g_pp);
    cudaGetSymbolAddress((void**)&ph,    g_h);

    float* emb = (float*)d_out;
    float* mu  = emb + (size_t)ROWS * DD;
    float* lv  = mu + BB * LAT;

    // x = feats @ projW + projB + posenc
    {
        dim3 grid(DD / 128, ROWS / 128);
        gemm_tf32<2><<<grid, 256>>>(feats, projW, projB, posenc, px, ROWS, DD, INF_);
    }

    for (int l = 0; l < LL; l++) {
        {
            dim3 grid((3 * DD) / 128, ROWS / 128);
            gemm_tf32<0><<<grid, 256>>>(px, qkvW + (size_t)l * DD * 3 * DD,
                                        qkvB + l * 3 * DD, nullptr, pqkv,
                                        ROWS, 3 * DD, DD);
        }
        banded_attn<<<(BB * HH * TT) / 8, 256>>>(pqkv, pctx);
        {
            dim3 grid(DD / 128, ROWS / 128);
            gemm_tf32<0><<<grid, 256>>>(pctx, outW + (size_t)l * DD * DD,
                                        outB + l * DD, nullptr, ptmp, ROWS, DD, DD);
        }
        add_ln<<<ROWS, 128>>>(px, ptmp, ln1s + l * DD, ln1b + l * DD, px);
        {
            dim3 grid(FF_ / 128, ROWS / 128);
            gemm_tf32<1><<<grid, 256>>>(px, ff1W + (size_t)l * DD * FF_,
                                        ff1B + l * FF_, nullptr, pff, ROWS, FF_, DD);
        }
        {
            dim3 grid(DD / 128, ROWS / 128);
            gemm_tf32<0><<<grid, 256>>>(pff, ff2W + (size_t)l * FF_ * DD,
                                        ff2B + l * DD, nullptr, ptmp, ROWS, DD, FF_);
        }
        float* dst = (l == LL - 1) ? emb : px;
        add_ln<<<ROWS, 128>>>(px, ptmp, ln2s + l * DD, ln2b + l * DD, dst);
    }

    pool_partial<<<BB * 32, DD>>>(emb, ppp);
    pool_reduce<<<BB, DD>>>(ppp, ppool);
    small_linear<<<BB, 2 * LAT>>>(ppool, mu1W, mu1B, ph, DD, 2 * LAT, 1);
    small_linear<<<BB, LAT>>>(ph, mu2W, mu2B, mu, 2 * LAT, LAT, 0);
    small_linear<<<BB, 2 * LAT>>>(ppool, lv1W, lv1B, ph, DD, 2 * LAT, 1);
    small_linear<<<BB, LAT>>>(ph, lv2W, lv2B, lv, 2 * LAT, LAT, 0);
}

// round 3
// speedup vs baseline: 2.6993x; 1.5201x over previous
#include <cuda_runtime.h>
#include <math.h>
#include <stdint.h>

// Problem constants
#define BB 4
#define TT 2048
#define INF_ 64
#define DD 512
#define HH 8
#define DH 64
#define FF_ 2048
#define LL 4
#define LAT 128
#define PAST 40
#define FUT 120
#define ROWS (BB*TT)          // 8192
#define EPS 1e-5f

// ---------------- scratch (device globals; no allocation allowed) ----------
__device__ float g_x   [ROWS * DD];
__device__ float g_qkv [ROWS * 3 * DD];
__device__ float g_ctx [ROWS * DD];
__device__ float g_tmp [ROWS * DD];
__device__ float g_ff  [ROWS * FF_];
__device__ float g_pool[BB * DD];
__device__ float g_pp  [BB * 32 * DD];
__device__ float g_h   [BB * 2 * LAT];

// ---------------- helpers ---------------------------------------------------
__device__ __forceinline__ float f2tf(float x) {
    uint32_t u;
    asm("cvt.rna.tf32.f32 %0, %1;" : "=r"(u) : "f"(x));
    return __uint_as_float(u);
}
__device__ __forceinline__ uint32_t f2tfu(float x) {
    uint32_t u;
    asm("cvt.rna.tf32.f32 %0, %1;" : "=r"(u) : "f"(x));
    return u;
}

#define MMA_TF32(d0,d1,d2,d3,a0,a1,a2,a3,b0,b1)                              \
    asm volatile("mma.sync.aligned.m16n8k8.row.col.f32.tf32.tf32.f32 "       \
        "{%0,%1,%2,%3},{%4,%5,%6,%7},{%8,%9},{%0,%1,%2,%3};"                 \
        : "+f"(d0),"+f"(d1),"+f"(d2),"+f"(d3)                                \
        : "r"(a0),"r"(a1),"r"(a2),"r"(a3),"r"(b0),"r"(b1))

// ---------------- TF32 tensor-core GEMM: C = A[M,K] @ B[K,N] + bias ---------
// EPI: 0 = +bias ; 1 = +bias, relu ; 2 = +bias + pos_enc[row%T]
template <int EPI>
__global__ __launch_bounds__(256)
void gemm_tf32(const float* __restrict__ A, const float* __restrict__ B,
               const float* __restrict__ bias, const float* __restrict__ extra,
               float* __restrict__ C, int M, int N, int K)
{
    constexpr int BM = 128, BN = 128, BK = 16;
    __shared__ float As[2][BM][BK + 4];
    __shared__ float Bs[2][BK][BN + 4];

    const int tid  = threadIdx.x;
    const int wid  = tid >> 5, lane = tid & 31;
    const int g    = lane >> 2, c = lane & 3;
    const int wm   = (wid >> 2) * 64;
    const int wn   = (wid & 3) * 32;
    const int brow = blockIdx.y * BM, bcol = blockIdx.x * BN;

    const int arow = tid >> 1,  acol  = (tid & 1) * 8;
    const int brw  = tid >> 4,  bcl   = (tid & 15) * 8;

    const float* Ag = A + (size_t)(brow + arow) * K + acol;
    const float* Bg = B + (size_t)brw * N + bcol + bcl;

    float4 pa0, pa1, pb0, pb1;
    pa0 = *(const float4*)(Ag);
    pa1 = *(const float4*)(Ag + 4);
    pb0 = *(const float4*)(Bg);
    pb1 = *(const float4*)(Bg + 4);

    float acc[4][4][4];
#pragma unroll
    for (int i = 0; i < 4; i++)
#pragma unroll
        for (int j = 0; j < 4; j++)
#pragma unroll
            for (int r = 0; r < 4; r++) acc[i][j][r] = 0.f;

    {
        float* pA = &As[0][arow][acol];
        pA[0]=f2tf(pa0.x); pA[1]=f2tf(pa0.y); pA[2]=f2tf(pa0.z); pA[3]=f2tf(pa0.w);
        pA[4]=f2tf(pa1.x); pA[5]=f2tf(pa1.y); pA[6]=f2tf(pa1.z); pA[7]=f2tf(pa1.w);
        float* pB = &Bs[0][brw][bcl];
        pB[0]=f2tf(pb0.x); pB[1]=f2tf(pb0.y); pB[2]=f2tf(pb0.z); pB[3]=f2tf(pb0.w);
        pB[4]=f2tf(pb1.x); pB[5]=f2tf(pb1.y); pB[6]=f2tf(pb1.z); pB[7]=f2tf(pb1.w);
    }
    __syncthreads();

    const int nk = K / BK;
    int buf = 0;
    for (int k0 = 0; k0 < nk; k0++) {
        if (k0 + 1 < nk) {
            const float* Agn = Ag + (k0 + 1) * BK;
            const float* Bgn = Bg + (size_t)(k0 + 1) * BK * N;
            pa0 = *(const float4*)(Agn);
            pa1 = *(const float4*)(Agn + 4);
            pb0 = *(const float4*)(Bgn);
            pb1 = *(const float4*)(Bgn + 4);
        }

#pragma unroll
        for (int kk = 0; kk < 2; kk++) {
            uint32_t af[4][4];
#pragma unroll
            for (int mt = 0; mt < 4; mt++) {
                const int m0 = wm + mt * 16 + g;
                af[mt][0] = __float_as_uint(As[buf][m0    ][kk*8 + c    ]);
                af[mt][1] = __float_as_uint(As[buf][m0 + 8][kk*8 + c    ]);
                af[mt][2] = __float_as_uint(As[buf][m0    ][kk*8 + c + 4]);
                af[mt][3] = __float_as_uint(As[buf][m0 + 8][kk*8 + c + 4]);
            }
            uint32_t bf[4][2];
#pragma unroll
            for (int nt = 0; nt < 4; nt++) {
                const int n0 = wn + nt * 8 + g;
                bf[nt][0] = __float_as_uint(Bs[buf][kk*8 + c    ][n0]);
                bf[nt][1] = __float_as_uint(Bs[buf][kk*8 + c + 4][n0]);
            }
#pragma unroll
            for (int mt = 0; mt < 4; mt++)
#pragma unroll
                for (int nt = 0; nt < 4; nt++)
                    MMA_TF32(acc[mt][nt][0], acc[mt][nt][1], acc[mt][nt][2], acc[mt][nt][3],
                             af[mt][0], af[mt][1], af[mt][2], af[mt][3],
                             bf[nt][0], bf[nt][1]);
        }

        if (k0 + 1 < nk) {
            const int nb = buf ^ 1;
            float* pA = &As[nb][arow][acol];
            pA[0]=f2tf(pa0.x); pA[1]=f2tf(pa0.y); pA[2]=f2tf(pa0.z); pA[3]=f2tf(pa0.w);
            pA[4]=f2tf(pa1.x); pA[5]=f2tf(pa1.y); pA[6]=f2tf(pa1.z); pA[7]=f2tf(pa1.w);
            float* pB = &Bs[nb][brw][bcl];
            pB[0]=f2tf(pb0.x); pB[1]=f2tf(pb0.y); pB[2]=f2tf(pb0.z); pB[3]=f2tf(pb0.w);
            pB[4]=f2tf(pb1.x); pB[5]=f2tf(pb1.y); pB[6]=f2tf(pb1.z); pB[7]=f2tf(pb1.w);
            __syncthreads();
            buf = nb;
        }
    }

#pragma unroll
    for (int mt = 0; mt < 4; mt++) {
#pragma unroll
        for (int nt = 0; nt < 4; nt++) {
            const int col = bcol + wn + nt * 8 + 2 * c;
            const float b0 = bias[col], b1 = bias[col + 1];
#pragma unroll
            for (int half = 0; half < 2; half++) {
                const int row = brow + wm + mt * 16 + g + half * 8;
                float v0 = acc[mt][nt][half * 2 + 0] + b0;
                float v1 = acc[mt][nt][half * 2 + 1] + b1;
                if (EPI == 1) { v0 = fmaxf(v0, 0.f); v1 = fmaxf(v1, 0.f); }
                if (EPI == 2) {
                    const int t = row & (TT - 1);
                    v0 += extra[(size_t)t * N + col];
                    v1 += extra[(size_t)t * N + col + 1];
                }
                float2 o; o.x = v0; o.y = v1;
                *(float2*)(C + (size_t)row * N + col) = o;
            }
        }
    }
}

// ---------------- banded flash attention (tensor core, TF32) ----------------
// Block: 64 queries of one (b,h). 4 warps, 16 query rows each.
// Key window covered by 4 aligned 64-key chunks: q0, q0-64, q0+64, q0+128.
__global__ __launch_bounds__(128)
void attn_mma(const float* __restrict__ qkv, float* __restrict__ ctx)
{
    const int blk = blockIdx.x;
    const int qt = blk & 31;
    const int h  = (blk >> 5) & 7;
    const int b  = blk >> 8;
    const int q0 = qt * 64;

    const int tid = threadIdx.x, wid = tid >> 5, lane = tid & 31;
    const int g = lane >> 2, c = lane & 3;

    __shared__ float Ks[64][68];   // K chunk [key][dh]; reused as P [q][key]
    __shared__ float Vs[64][68];   // V chunk transposed [dh][key]

    // ---- load Q fragments (16 rows per warp), convert to tf32
    const int i0 = q0 + wid * 16;
    const size_t qkv_row = (size_t)1536;
    uint32_t qa[8][4];
#pragma unroll
    for (int kt = 0; kt < 8; kt++) {
        const float* q_lo = qkv + (size_t)(b * TT + i0 + g    ) * qkv_row + h * 64 + kt * 8;
        const float* q_hi = qkv + (size_t)(b * TT + i0 + g + 8) * qkv_row + h * 64 + kt * 8;
        qa[kt][0] = f2tfu(q_lo[c]);
        qa[kt][1] = f2tfu(q_hi[c]);
        qa[kt][2] = f2tfu(q_lo[c + 4]);
        qa[kt][3] = f2tfu(q_hi[c + 4]);
    }

    float oacc[8][4];
#pragma unroll
    for (int nt = 0; nt < 8; nt++)
#pragma unroll
        for (int e = 0; e < 4; e++) oacc[nt][e] = 0.f;

    float m0 = -INFINITY, m1 = -INFINITY, l0 = 0.f, l1 = 0.f;
    const int r0 = i0 + g, r1 = i0 + g + 8;   // global query rows of this thread
    const float scale = 0.125f;

    // chunk starts; first chunk (cs = q0) guarantees every row sees valid keys
    const int chunk_off[4] = {0, -64, 64, 128};

#pragma unroll 1
    for (int ci = 0; ci < 4; ci++) {
        const int cs = q0 + chunk_off[ci];
        if (cs < 0 || cs >= TT) continue;   // uniform across block

        __syncthreads();   // previous-iter Ps/Vs consumers done

        // ---- load K chunk -> Ks[key][dh], V chunk (transposed) -> Vs[dh][key]
        {
            const int key   = tid >> 1;
            const int cbase = (tid & 1) * 32;
            const float* krow = qkv + (size_t)(b * TT + cs + key) * qkv_row + 512  + h * 64 + cbase;
            const float* vrow = qkv + (size_t)(b * TT + cs + key) * qkv_row + 1024 + h * 64 + cbase;
#pragma unroll
            for (int i = 0; i < 8; i++) {
                float4 kv = *(const float4*)(krow + i * 4);
                float4 o;
                o.x = f2tf(kv.x); o.y = f2tf(kv.y); o.z = f2tf(kv.z); o.w = f2tf(kv.w);
                *(float4*)&Ks[key][cbase + i * 4] = o;
                float4 vv = *(const float4*)(vrow + i * 4);
                Vs[cbase + i * 4 + 0][key] = f2tf(vv.x);
                Vs[cbase + i * 4 + 1][key] = f2tf(vv.y);
                Vs[cbase + i * 4 + 2][key] = f2tf(vv.z);
                Vs[cbase + i * 4 + 3][key] = f2tf(vv.w);
            }
        }
        __syncthreads();

        // ---- S = Q @ K^T   (16 x 64 per warp)
        float sacc[8][4];
#pragma unroll
        for (int nt = 0; nt < 8; nt++)
#pragma unroll
            for (int e = 0; e < 4; e++) sacc[nt][e] = 0.f;

#pragma unroll
        for (int nt = 0; nt < 8; nt++) {
#pragma unroll
            for (int kt = 0; kt < 8; kt++) {
                uint32_t b0 = __float_as_uint(Ks[nt * 8 + g][kt * 8 + c]);
                uint32_t b1 = __float_as_uint(Ks[nt * 8 + g][kt * 8 + c + 4]);
                MMA_TF32(sacc[nt][0], sacc[nt][1], sacc[nt][2], sacc[nt][3],
                         qa[kt][0], qa[kt][1], qa[kt][2], qa[kt][3], b0, b1);
            }
        }

        // ---- mask + row max
        float mx0 = -INFINITY, mx1 = -INFINITY;
#pragma unroll
        for (int nt = 0; nt < 8; nt++) {
            const int j0 = cs + nt * 8 + 2 * c;
            const int j1 = j0 + 1;
            float v;
            v = sacc[nt][0] * scale;
            v = (j0 >= r0 - PAST && j0 <= r0 + FUT) ? v : -INFINITY;
            sacc[nt][0] = v; mx0 = fmaxf(mx0, v);
            v = sacc[nt][1] * scale;
            v = (j1 >= r0 - PAST && j1 <= r0 + FUT) ? v : -INFINITY;
            sacc[nt][1] = v; mx0 = fmaxf(mx0, v);
            v = sacc[nt][2] * scale;
            v = (j0 >= r1 - PAST && j0 <= r1 + FUT) ? v : -INFINITY;
            sacc[nt][2] = v; mx1 = fmaxf(mx1, v);
            v = sacc[nt][3] * scale;
            v = (j1 >= r1 - PAST && j1 <= r1 + FUT) ? v : -INFINITY;
            sacc[nt][3] = v; mx1 = fmaxf(mx1, v);
        }
        mx0 = fmaxf(mx0, __shfl_xor_sync(0xffffffffu, mx0, 1));
        mx0 = fmaxf(mx0, __shfl_xor_sync(0xffffffffu, mx0, 2));
        mx1 = fmaxf(mx1, __shfl_xor_sync(0xffffffffu, mx1, 1));
        mx1 = fmaxf(mx1, __shfl_xor_sync(0xffffffffu, mx1, 2));

        const float mn0 = fmaxf(m0, mx0);
        const float mn1 = fmaxf(m1, mx1);
        const float rf0 = __expf(m0 - mn0);   // first chunk: exp(-inf) = 0
        const float rf1 = __expf(m1 - mn1);
        m0 = mn0; m1 = mn1;

        // ---- p = exp(s - m), row sums, write P to smem (aliased over Ks)
        __syncthreads();   // all warps finished reading Ks for S
        float ps0 = 0.f, ps1 = 0.f;
#pragma unroll
        for (int nt = 0; nt < 8; nt++) {
            float p00 = __expf(sacc[nt][0] - mn0);
            float p01 = __expf(sacc[nt][1] - mn0);
            float p10 = __expf(sacc[nt][2] - mn1);
            float p11 = __expf(sacc[nt][3] - mn1);
            ps0 += p00 + p01;
            ps1 += p10 + p11;
            float2 w;
            w.x = f2tf(p00); w.y = f2tf(p01);
            *(float2*)&Ks[wid * 16 + g    ][nt * 8 + 2 * c] = w;
            w.x = f2tf(p10); w.y = f2tf(p11);
            *(float2*)&Ks[wid * 16 + g + 8][nt * 8 + 2 * c] = w;
        }
        ps0 += __shfl_xor_sync(0xffffffffu, ps0, 1);
        ps0 += __shfl_xor_sync(0xffffffffu, ps0, 2);
        ps1 += __shfl_xor_sync(0xffffffffu, ps1, 1);
        ps1 += __shfl_xor_sync(0xffffffffu, ps1, 2);
        l0 = l0 * rf0 + ps0;
        l1 = l1 * rf1 + ps1;

        // rescale O accumulators
#pragma unroll
        for (int nt = 0; nt < 8; nt++) {
            oacc[nt][0] *= rf0; oacc[nt][1] *= rf0;
            oacc[nt][2] *= rf1; oacc[nt][3] *= rf1;
        }
        __syncwarp();   // P stores visible to this warp's lanes

        // ---- O += P @ V   (A = P rows of this warp, B = Vs[dh][key] col-major)
#pragma unroll
        for (int nt = 0; nt < 8; nt++) {
#pragma unroll
            for (int kt = 0; kt < 8; kt++) {
                uint32_t a0 = __float_as_uint(Ks[wid * 16 + g    ][kt * 8 + c    ]);
                uint32_t a1 = __float_as_uint(Ks[wid * 16 + g + 8][kt * 8 + c    ]);
                uint32_t a2 = __float_as_uint(Ks[wid * 16 + g    ][kt * 8 + c + 4]);
                uint32_t a3 = __float_as_uint(Ks[wid * 16 + g + 8][kt * 8 + c + 4]);
                uint32_t b0 = __float_as_uint(Vs[nt * 8 + g][kt * 8 + c]);
                uint32_t b1 = __float_as_uint(Vs[nt * 8 + g][kt * 8 + c + 4]);
                MMA_TF32(oacc[nt][0], oacc[nt][1], oacc[nt][2], oacc[nt][3],
                         a0, a1, a2, a3, b0, b1);
            }
        }
    }

    // ---- write O / l
    const float inv0 = 1.f / l0, inv1 = 1.f / l1;
#pragma unroll
    for (int nt = 0; nt < 8; nt++) {
        const int col = h * 64 + nt * 8 + 2 * c;
        float2 w;
        w.x = oacc[nt][0] * inv0; w.y = oacc[nt][1] * inv0;
        *(float2*)(ctx + (size_t)(b * TT + r0) * DD + col) = w;
        w.x = oacc[nt][2] * inv1; w.y = oacc[nt][3] * inv1;
        *(float2*)(ctx + (size_t)(b * TT + r1) * DD + col) = w;
    }
}

// ---------------- residual add + LayerNorm (row = 512) ---------------------
__global__ __launch_bounds__(128)
void add_ln(const float* __restrict__ x, const float* __restrict__ y,
            const float* __restrict__ s, const float* __restrict__ bta,
            float* __restrict__ out)
{
    const int row = blockIdx.x;
    const int tid = threadIdx.x;
    float v[4];
    float sum = 0.f, sq = 0.f;
#pragma unroll
    for (int i = 0; i < 4; i++) {
        int c = tid + i * 128;
        float val = x[(size_t)row * DD + c] + y[(size_t)row * DD + c];
        v[i] = val;
        sum += val;
        sq  += val * val;
    }
    __shared__ float rs[8];
#pragma unroll
    for (int off = 16; off > 0; off >>= 1) {
        sum += __shfl_xor_sync(0xffffffffu, sum, off);
        sq  += __shfl_xor_sync(0xffffffffu, sq,  off);
    }
    if ((tid & 31) == 0) { rs[tid >> 5] = sum; rs[4 + (tid >> 5)] = sq; }
    __syncthreads();
    sum = rs[0] + rs[1] + rs[2] + rs[3];
    sq  = rs[4] + rs[5] + rs[6] + rs[7];
    const float mean = sum * (1.f / DD);
    const float var  = sq * (1.f / DD) - mean * mean;
    const float inv  = rsqrtf(var + EPS);
#pragma unroll
    for (int i = 0; i < 4; i++) {
        int c = tid + i * 128;
        out[(size_t)row * DD + c] = (v[i] - mean) * inv * s[c] + bta[c];
    }
}

// ---------------- mean pool (two-stage) -------------------------------------
__global__ void pool_partial(const float* __restrict__ emb, float* __restrict__ pp)
{
    const int b = blockIdx.x >> 5, ch = blockIdx.x & 31;
    const int d = threadIdx.x;
    float s = 0.f;
    const int t0 = ch * 64;
    for (int t = t0; t < t0 + 64; t++)
        s += emb[((size_t)(b * TT + t)) * DD + d];
    pp[(size_t)blockIdx.x * DD + d] = s;
}

__global__ void pool_reduce(const float* __restrict__ pp, float* __restrict__ p)
{
    const int b = blockIdx.x, d = threadIdx.x;
    float s = 0.f;
    for (int ch = 0; ch < 32; ch++)
        s += pp[(size_t)(b * 32 + ch) * DD + d];
    p[b * DD + d] = s * (1.f / TT);
}

// ---------------- tiny dense layer (heads) ----------------------------------
__global__ void small_linear(const float* __restrict__ in, const float* __restrict__ W,
                             const float* __restrict__ bias, float* __restrict__ out,
                             int K, int N, int relu)
{
    const int b = blockIdx.x, n = threadIdx.x;
    if (n >= N) return;
    float sum = bias[n];
    for (int k = 0; k < K; k++)
        sum = fmaf(in[b * K + k], W[(size_t)k * N + n], sum);
    if (relu) sum = fmaxf(sum, 0.f);
    out[b * N + n] = sum;
}

// ---------------- launch -----------------------------------------------------
extern "C" void kernel_launch(void* const* d_in, const int* in_sizes, int n_in,
                              void* d_out, int out_size)
{
    const float* feats  = (const float*)d_in[0];
    const float* projW  = (const float*)d_in[1];
    const float* projB  = (const float*)d_in[2];
    const float* posenc = (const float*)d_in[3];
    const float* qkvW   = (const float*)d_in[4];
    const float* qkvB   = (const float*)d_in[5];
    const float* outW   = (const float*)d_in[6];
    const float* outB   = (const float*)d_in[7];
    const float* ln1s   = (const float*)d_in[8];
    const float* ln1b   = (const float*)d_in[9];
    const float* ff1W   = (const float*)d_in[10];
    const float* ff1B   = (const float*)d_in[11];
    const float* ff2W   = (const float*)d_in[12];
    const float* ff2B   = (const float*)d_in[13];
    const float* ln2s   = (const float*)d_in[14];
    const float* ln2b   = (const float*)d_in[15];
    const float* mu1W   = (const float*)d_in[16];
    const float* mu1B   = (const float*)d_in[17];
    const float* mu2W   = (const float*)d_in[18];
    const float* mu2B   = (const float*)d_in[19];
    const float* lv1W   = (const float*)d_in[20];
    const float* lv1B   = (const float*)d_in[21];
    const float* lv2W   = (const float*)d_in[22];
    const float* lv2B   = (const float*)d_in[23];

    float *px, *pqkv, *pctx, *ptmp, *pff, *ppool, *ppp, *ph;
    cudaGetSymbolAddress((void**)&px,    g_x);
    cudaGetSymbolAddress((void**)&pqkv,  g_qkv);
    cudaGetSymbolAddress((void**)&pctx,  g_ctx);
    cudaGetSymbolAddress((void**)&ptmp,  g_tmp);
    cudaGetSymbolAddress((void**)&pff,   g_ff);
    cudaGetSymbolAddress((void**)&ppool, g_pool);
    cudaGetSymbolAddress((void**)&ppp,   g_pp);
    cudaGetSymbolAddress((void**)&ph,    g_h);

    float* emb = (float*)d_out;
    float* mu  = emb + (size_t)ROWS * DD;
    float* lv  = mu + BB * LAT;

    // x = feats @ projW + projB + posenc
    {
        dim3 grid(DD / 128, ROWS / 128);
        gemm_tf32<2><<<grid, 256>>>(feats, projW, projB, posenc, px, ROWS, DD, INF_);
    }

    for (int l = 0; l < LL; l++) {
        {
            dim3 grid((3 * DD) / 128, ROWS / 128);
            gemm_tf32<0><<<grid, 256>>>(px, qkvW + (size_t)l * DD * 3 * DD,
                                        qkvB + l * 3 * DD, nullptr, pqkv,
                                        ROWS, 3 * DD, DD);
        }
        attn_mma<<<BB * HH * 32, 128>>>(pqkv, pctx);
        {
            dim3 grid(DD / 128, ROWS / 128);
            gemm_tf32<0><<<grid, 256>>>(pctx, outW + (size_t)l * DD * DD,
                                        outB + l * DD, nullptr, ptmp, ROWS, DD, DD);
        }
        add_ln<<<ROWS, 128>>>(px, ptmp, ln1s + l * DD, ln1b + l * DD, px);
        {
            dim3 grid(FF_ / 128, ROWS / 128);
            gemm_tf32<1><<<grid, 256>>>(px, ff1W + (size_t)l * DD * FF_,
                                        ff1B + l * FF_, nullptr, pff, ROWS, FF_, DD);
        }
        {
            dim3 grid(DD / 128, ROWS / 128);
            gemm_tf32<0><<<grid, 256>>>(pff, ff2W + (size_t)l * FF_ * DD,
                                        ff2B + l * DD, nullptr, ptmp, ROWS, DD, FF_);
        }
        float* dst = (l == LL - 1) ? emb : px;
        add_ln<<<ROWS, 128>>>(px, ptmp, ln2s + l * DD, ln2b + l * DD, dst);
    }

    pool_partial<<<BB * 32, DD>>>(emb, ppp);
    pool_reduce<<<BB, DD>>>(ppp, ppool);
    small_linear<<<BB, 2 * LAT>>>(ppool, mu1W, mu1B, ph, DD, 2 * LAT, 1);
    small_linear<<<BB, LAT>>>(ph, mu2W, mu2B, mu, 2 * LAT, LAT, 0);
    small_linear<<<BB, 2 * LAT>>>(ppool, lv1W, lv1B, ph, DD, 2 * LAT, 1);
    small_linear<<<BB, LAT>>>(ph, lv2W, lv2B, lv, 2 * LAT, LAT, 0);
}

// round 4
// speedup vs baseline: 2.7063x; 1.0026x over previous
#include <cuda_runtime.h>
#include <math.h>
#include <stdint.h>

// Problem constants
#define BB 4
#define TT 2048
#define INF_ 64
#define DD 512
#define HH 8
#define DH 64
#define FF_ 2048
#define LL 4
#define LAT 128
#define PAST 40
#define FUT 120
#define ROWS (BB*TT)          // 8192
#define EPS 1e-5f

// ---------------- scratch (device globals; no allocation allowed) ----------
__device__ float g_x   [ROWS * DD];
__device__ float g_qkv [ROWS * 3 * DD];
__device__ float g_ctx [ROWS * DD];
__device__ float g_tmp [ROWS * DD];
__device__ float g_ff  [ROWS * FF_];
__device__ float g_pool[BB * DD];
__device__ float g_pp  [BB * 32 * DD];
__device__ float g_h   [BB * 2 * LAT];

// ---------------- helpers ---------------------------------------------------
__device__ __forceinline__ float f2tf(float x) {
    uint32_t u;
    asm("cvt.rna.tf32.f32 %0, %1;" : "=r"(u) : "f"(x));
    return __uint_as_float(u);
}
__device__ __forceinline__ uint32_t f2tfu(float x) {
    uint32_t u;
    asm("cvt.rna.tf32.f32 %0, %1;" : "=r"(u) : "f"(x));
    return u;
}
__device__ __forceinline__ uint32_t sptr(const void* p) {
    return (uint32_t)__cvta_generic_to_shared(p);
}
__device__ __forceinline__ void cpa16(uint32_t dst, const void* src) {
    asm volatile("cp.async.cg.shared.global [%0], [%1], 16;\n" :: "r"(dst), "l"(src));
}
#define CP_COMMIT() asm volatile("cp.async.commit_group;\n")
#define CP_WAIT(n)  asm volatile("cp.async.wait_group %0;\n" :: "n"(n))

#define MMA_TF32(d0,d1,d2,d3,a0,a1,a2,a3,b0,b1)                              \
    asm volatile("mma.sync.aligned.m16n8k8.row.col.f32.tf32.tf32.f32 "       \
        "{%0,%1,%2,%3},{%4,%5,%6,%7},{%8,%9},{%0,%1,%2,%3};"                 \
        : "+f"(d0),"+f"(d1),"+f"(d2),"+f"(d3)                                \
        : "r"(a0),"r"(a1),"r"(a2),"r"(a3),"r"(b0),"r"(b1))

// ---------------- TF32 tensor-core GEMM, 3-stage cp.async pipeline ----------
// EPI: 0 = +bias ; 1 = +bias, relu ; 2 = +bias + pos_enc[row%T]
#define GEMM_APAD 20
#define GEMM_BPAD 136
#define GEMM_ASZ  (128 * GEMM_APAD)          // floats per A stage (2560)
#define GEMM_BSZ  (16 * GEMM_BPAD)           // floats per B stage (2176)
#define GEMM_SMEM (3 * (GEMM_ASZ + GEMM_BSZ) * 4)   // 56832 B

template <int EPI>
__global__ __launch_bounds__(256)
void gemm_tf32(const float* __restrict__ A, const float* __restrict__ B,
               const float* __restrict__ bias, const float* __restrict__ extra,
               float* __restrict__ C, int M, int N, int K)
{
    constexpr int BM = 128, BN = 128, BK = 16;
    extern __shared__ float sm[];
    float* As = sm;                          // [3][128][20]
    float* Bs = sm + 3 * GEMM_ASZ;           // [3][16][136]

    const int tid  = threadIdx.x;
    const int wid  = tid >> 5, lane = tid & 31;
    const int g    = lane >> 2, c = lane & 3;
    const int wm   = (wid >> 2) * 64;
    const int wn   = (wid & 3) * 32;
    const int brow = blockIdx.y * BM, bcol = blockIdx.x * BN;

    const int arow = tid >> 1,  acol = (tid & 1) * 8;
    const int brw  = tid >> 4,  bcl  = (tid & 15) * 8;

    const float* Ag = A + (size_t)(brow + arow) * K + acol;
    const float* Bg = B + bcol + bcl;

    const uint32_t sA = sptr(As) + (uint32_t)(arow * GEMM_APAD + acol) * 4u;
    const uint32_t sB = sptr(Bs) + (uint32_t)(brw * GEMM_BPAD + bcl) * 4u;

    float acc[4][4][4];
#pragma unroll
    for (int i = 0; i < 4; i++)
#pragma unroll
        for (int j = 0; j < 4; j++)
#pragma unroll
            for (int r = 0; r < 4; r++) acc[i][j][r] = 0.f;

    const int nk = K / BK;

    // prologue: stages 0 and 1
    {
        cpa16(sA, Ag);       cpa16(sA + 16, Ag + 4);
        cpa16(sB, Bg + (size_t)brw * N);
        cpa16(sB + 16, Bg + (size_t)brw * N + 4);
        CP_COMMIT();
        if (nk > 1) {
            cpa16(sA + GEMM_ASZ * 4, Ag + BK);
            cpa16(sA + GEMM_ASZ * 4 + 16, Ag + BK + 4);
            cpa16(sB + GEMM_BSZ * 4, Bg + (size_t)(BK + brw) * N);
            cpa16(sB + GEMM_BSZ * 4 + 16, Bg + (size_t)(BK + brw) * N + 4);
            CP_COMMIT();
            CP_WAIT(1);
        } else {
            CP_WAIT(0);
        }
        __syncthreads();
    }

    int s_cur = 0;
    for (int k0 = 0; k0 < nk; k0++) {
        // issue stage k0+2 into slot (s_cur+2)%3 (freed by sync at end of k0-1)
        if (k0 + 2 < nk) {
            const int s = (s_cur + 2 >= 3) ? s_cur - 1 : s_cur + 2;
            const float* ga = Ag + (k0 + 2) * BK;
            cpa16(sA + s * GEMM_ASZ * 4, ga);
            cpa16(sA + s * GEMM_ASZ * 4 + 16, ga + 4);
            const float* gb = Bg + (size_t)((k0 + 2) * BK + brw) * N;
            cpa16(sB + s * GEMM_BSZ * 4, gb);
            cpa16(sB + s * GEMM_BSZ * 4 + 16, gb + 4);
            CP_COMMIT();
        }

        const float* Ab = As + s_cur * GEMM_ASZ;
        const float* Bb = Bs + s_cur * GEMM_BSZ;
#pragma unroll
        for (int kk = 0; kk < 2; kk++) {
            uint32_t af[4][4];
#pragma unroll
            for (int mt = 0; mt < 4; mt++) {
                const int m0 = wm + mt * 16 + g;
                af[mt][0] = f2tfu(Ab[(m0    ) * GEMM_APAD + kk * 8 + c    ]);
                af[mt][1] = f2tfu(Ab[(m0 + 8) * GEMM_APAD + kk * 8 + c    ]);
                af[mt][2] = f2tfu(Ab[(m0    ) * GEMM_APAD + kk * 8 + c + 4]);
                af[mt][3] = f2tfu(Ab[(m0 + 8) * GEMM_APAD + kk * 8 + c + 4]);
            }
            uint32_t bf[4][2];
#pragma unroll
            for (int nt = 0; nt < 4; nt++) {
                const int n0 = wn + nt * 8 + g;
                bf[nt][0] = f2tfu(Bb[(kk * 8 + c    ) * GEMM_BPAD + n0]);
                bf[nt][1] = f2tfu(Bb[(kk * 8 + c + 4) * GEMM_BPAD + n0]);
            }
#pragma unroll
            for (int mt = 0; mt < 4; mt++)
#pragma unroll
                for (int nt = 0; nt < 4; nt++)
                    MMA_TF32(acc[mt][nt][0], acc[mt][nt][1], acc[mt][nt][2], acc[mt][nt][3],
                             af[mt][0], af[mt][1], af[mt][2], af[mt][3],
                             bf[nt][0], bf[nt][1]);
        }

        if (k0 + 1 < nk) {
            if (k0 + 2 < nk) CP_WAIT(1); else CP_WAIT(0);
            __syncthreads();
        }
        s_cur = (s_cur + 1 >= 3) ? 0 : s_cur + 1;
    }

    // epilogue
#pragma unroll
    for (int mt = 0; mt < 4; mt++) {
#pragma unroll
        for (int nt = 0; nt < 4; nt++) {
            const int col = bcol + wn + nt * 8 + 2 * c;
            const float b0 = bias[col], b1 = bias[col + 1];
#pragma unroll
            for (int half = 0; half < 2; half++) {
                const int row = brow + wm + mt * 16 + g + half * 8;
                float v0 = acc[mt][nt][half * 2 + 0] + b0;
                float v1 = acc[mt][nt][half * 2 + 1] + b1;
                if (EPI == 1) { v0 = fmaxf(v0, 0.f); v1 = fmaxf(v1, 0.f); }
                if (EPI == 2) {
                    const int t = row & (TT - 1);
                    v0 += extra[(size_t)t * N + col];
                    v1 += extra[(size_t)t * N + col + 1];
                }
                float2 o; o.x = v0; o.y = v1;
                *(float2*)(C + (size_t)row * N + col) = o;
            }
        }
    }
}

// ---------------- banded flash attention (tensor core, cp.async chunks) -----
// Block: 64 queries of one (b,h). 4 warps, 16 query rows each.
// Key window covered by up to 4 aligned 64-key chunks: q0, q0-64, q0+64, q0+128.
#define KVP 72
#define ABUF (64 * KVP)                       // floats per K or V buffer
#define ATTN_SMEM (5 * ABUF * 4)              // Ks[2] + Vs[2] + Ps  = 92160 B

__global__ __launch_bounds__(128)
void attn_mma(const float* __restrict__ qkv, float* __restrict__ ctx)
{
    extern __shared__ float sm[];
    float* Ks = sm;                 // [2][64][72]  raw K rows
    float* Vs = sm + 2 * ABUF;      // [2][64][72]  raw V rows
    float* Ps = sm + 4 * ABUF;      // [64][72]     tf32 P

    const int blk = blockIdx.x;
    const int qt = blk & 31;
    const int h  = (blk >> 5) & 7;
    const int b  = blk >> 8;
    const int q0 = qt * 64;

    const int tid = threadIdx.x, wid = tid >> 5, lane = tid & 31;
    const int g = lane >> 2, c = lane & 3;

    // ---- Q fragments (16 rows per warp), tf32
    const int i0 = q0 + wid * 16;
    uint32_t qa[8][4];
#pragma unroll
    for (int kt = 0; kt < 8; kt++) {
        const float* q_lo = qkv + (size_t)(b * TT + i0 + g    ) * 1536 + h * 64 + kt * 8;
        const float* q_hi = qkv + (size_t)(b * TT + i0 + g + 8) * 1536 + h * 64 + kt * 8;
        qa[kt][0] = f2tfu(q_lo[c]);
        qa[kt][1] = f2tfu(q_hi[c]);
        qa[kt][2] = f2tfu(q_lo[c + 4]);
        qa[kt][3] = f2tfu(q_hi[c + 4]);
    }

    float oacc[8][4];
#pragma unroll
    for (int nt = 0; nt < 8; nt++)
#pragma unroll
        for (int e = 0; e < 4; e++) oacc[nt][e] = 0.f;

    float m0 = -INFINITY, m1 = -INFINITY, l0 = 0.f, l1 = 0.f;
    const int r0 = i0 + g, r1 = i0 + g + 8;
    const float scale = 0.125f;

    // chunk list; cs = q0 first so every row's max is finite on chunk 0
    int csv[4]; int ncs = 0;
    const int offs[4] = {0, -64, 64, 128};
#pragma unroll
    for (int i = 0; i < 4; i++) {
        const int cs = q0 + offs[i];
        if (cs >= 0 && cs < TT) csv[ncs++] = cs;
    }

    // thread t<64 loads K row t; t>=64 loads V row t-64 (16B x 16 per row)
    const int lrow = tid & 63;
    const int isv  = tid >> 6;
    const uint32_t ldst0 = sptr((isv ? Vs : Ks) + lrow * KVP);
    const size_t  lsrc_off = (size_t)512 + (size_t)isv * 512 + h * 64;

    {   // prologue: chunk 0
        const float* src = qkv + (size_t)(b * TT + csv[0] + lrow) * 1536 + lsrc_off;
#pragma unroll
        for (int i = 0; i < 16; i++) cpa16(ldst0 + i * 16, src + i * 4);
        CP_COMMIT();
    }

    for (int ci = 0; ci < ncs; ci++) {
        CP_WAIT(0);
        __syncthreads();    // chunk ci visible to all; all warps past chunk ci-1 compute

        if (ci + 1 < ncs) {
            const uint32_t dst = ldst0 + ((ci + 1) & 1) * ABUF * 4;
            const float* src = qkv + (size_t)(b * TT + csv[ci + 1] + lrow) * 1536 + lsrc_off;
#pragma unroll
            for (int i = 0; i < 16; i++) cpa16(dst + i * 16, src + i * 4);
            CP_COMMIT();
        }

        const float* Kb = Ks + (ci & 1) * ABUF;
        const float* Vb = Vs + (ci & 1) * ABUF;
        const int cs = csv[ci];

        // ---- S = Q @ K^T
        float sacc[8][4];
#pragma unroll
        for (int nt = 0; nt < 8; nt++)
#pragma unroll
            for (int e = 0; e < 4; e++) sacc[nt][e] = 0.f;

#pragma unroll
        for (int nt = 0; nt < 8; nt++) {
#pragma unroll
            for (int kt = 0; kt < 8; kt++) {
                const uint32_t b0 = f2tfu(Kb[(nt * 8 + g) * KVP + kt * 8 + c]);
                const uint32_t b1 = f2tfu(Kb[(nt * 8 + g) * KVP + kt * 8 + c + 4]);
                MMA_TF32(sacc[nt][0], sacc[nt][1], sacc[nt][2], sacc[nt][3],
                         qa[kt][0], qa[kt][1], qa[kt][2], qa[kt][3], b0, b1);
            }
        }

        // ---- mask + row max
        float mx0 = -INFINITY, mx1 = -INFINITY;
#pragma unroll
        for (int nt = 0; nt < 8; nt++) {
            const int j0 = cs + nt * 8 + 2 * c;
            const int j1 = j0 + 1;
            float v;
            v = sacc[nt][0] * scale;
            v = (j0 >= r0 - PAST && j0 <= r0 + FUT) ? v : -INFINITY;
            sacc[nt][0] = v; mx0 = fmaxf(mx0, v);
            v = sacc[nt][1] * scale;
            v = (j1 >= r0 - PAST && j1 <= r0 + FUT) ? v : -INFINITY;
            sacc[nt][1] = v; mx0 = fmaxf(mx0, v);
            v = sacc[nt][2] * scale;
            v = (j0 >= r1 - PAST && j0 <= r1 + FUT) ? v : -INFINITY;
            sacc[nt][2] = v; mx1 = fmaxf(mx1, v);
            v = sacc[nt][3] * scale;
            v = (j1 >= r1 - PAST && j1 <= r1 + FUT) ? v : -INFINITY;
            sacc[nt][3] = v; mx1 = fmaxf(mx1, v);
        }
        mx0 = fmaxf(mx0, __shfl_xor_sync(0xffffffffu, mx0, 1));
        mx0 = fmaxf(mx0, __shfl_xor_sync(0xffffffffu, mx0, 2));
        mx1 = fmaxf(mx1, __shfl_xor_sync(0xffffffffu, mx1, 1));
        mx1 = fmaxf(mx1, __shfl_xor_sync(0xffffffffu, mx1, 2));

        const float mn0 = fmaxf(m0, mx0);
        const float mn1 = fmaxf(m1, mx1);
        const float rf0 = __expf(m0 - mn0);
        const float rf1 = __expf(m1 - mn1);
        m0 = mn0; m1 = mn1;

        // ---- p = exp(s-m) -> Ps (own rows only), row sums
        float ps0 = 0.f, ps1 = 0.f;
#pragma unroll
        for (int nt = 0; nt < 8; nt++) {
            const float p00 = __expf(sacc[nt][0] - mn0);
            const float p01 = __expf(sacc[nt][1] - mn0);
            const float p10 = __expf(sacc[nt][2] - mn1);
            const float p11 = __expf(sacc[nt][3] - mn1);
            ps0 += p00 + p01;
            ps1 += p10 + p11;
            float2 w;
            w.x = f2tf(p00); w.y = f2tf(p01);
            *(float2*)&Ps[(wid * 16 + g    ) * KVP + nt * 8 + 2 * c] = w;
            w.x = f2tf(p10); w.y = f2tf(p11);
            *(float2*)&Ps[(wid * 16 + g + 8) * KVP + nt * 8 + 2 * c] = w;
        }
        ps0 += __shfl_xor_sync(0xffffffffu, ps0, 1);
        ps0 += __shfl_xor_sync(0xffffffffu, ps0, 2);
        ps1 += __shfl_xor_sync(0xffffffffu, ps1, 1);
        ps1 += __shfl_xor_sync(0xffffffffu, ps1, 2);
        l0 = l0 * rf0 + ps0;
        l1 = l1 * rf1 + ps1;

#pragma unroll
        for (int nt = 0; nt < 8; nt++) {
            oacc[nt][0] *= rf0; oacc[nt][1] *= rf0;
            oacc[nt][2] *= rf1; oacc[nt][3] *= rf1;
        }
        __syncwarp();

        // ---- O += P @ V  (V row-major: b = V[key][dh])
#pragma unroll
        for (int nt = 0; nt < 8; nt++) {
#pragma unroll
            for (int kt = 0; kt < 8; kt++) {
                const uint32_t a0 = __float_as_uint(Ps[(wid * 16 + g    ) * KVP + kt * 8 + c    ]);
                const uint32_t a1 = __float_as_uint(Ps[(wid * 16 + g + 8) * KVP + kt * 8 + c    ]);
                const uint32_t a2 = __float_as_uint(Ps[(wid * 16 + g    ) * KVP + kt * 8 + c + 4]);
                const uint32_t a3 = __float_as_uint(Ps[(wid * 16 + g + 8) * KVP + kt * 8 + c + 4]);
                const uint32_t b0 = f2tfu(Vb[(kt * 8 + c    ) * KVP + nt * 8 + g]);
                const uint32_t b1 = f2tfu(Vb[(kt * 8 + c + 4) * KVP + nt * 8 + g]);
                MMA_TF32(oacc[nt][0], oacc[nt][1], oacc[nt][2], oacc[nt][3],
                         a0, a1, a2, a3, b0, b1);
            }
        }
    }

    // ---- write O
    const float inv0 = 1.f / l0, inv1 = 1.f / l1;
#pragma unroll
    for (int nt = 0; nt < 8; nt++) {
        const int col = h * 64 + nt * 8 + 2 * c;
        float2 w;
        w.x = oacc[nt][0] * inv0; w.y = oacc[nt][1] * inv0;
        *(float2*)(ctx + (size_t)(b * TT + r0) * DD + col) = w;
        w.x = oacc[nt][2] * inv1; w.y = oacc[nt][3] * inv1;
        *(float2*)(ctx + (size_t)(b * TT + r1) * DD + col) = w;
    }
}

// ---------------- residual add + LayerNorm (row = 512) ---------------------
__global__ __launch_bounds__(128)
void add_ln(const float* __restrict__ x, const float* __restrict__ y,
            const float* __restrict__ s, const float* __restrict__ bta,
            float* __restrict__ out)
{
    const int row = blockIdx.x;
    const int tid = threadIdx.x;
    float v[4];
    float sum = 0.f, sq = 0.f;
#pragma unroll
    for (int i = 0; i < 4; i++) {
        int c = tid + i * 128;
        float val = x[(size_t)row * DD + c] + y[(size_t)row * DD + c];
        v[i] = val;
        sum += val;
        sq  += val * val;
    }
    __shared__ float rs[8];
#pragma unroll
    for (int off = 16; off > 0; off >>= 1) {
        sum += __shfl_xor_sync(0xffffffffu, sum, off);
        sq  += __shfl_xor_sync(0xffffffffu, sq,  off);
    }
    if ((tid & 31) == 0) { rs[tid >> 5] = sum; rs[4 + (tid >> 5)] = sq; }
    __syncthreads();
    sum = rs[0] + rs[1] + rs[2] + rs[3];
    sq  = rs[4] + rs[5] + rs[6] + rs[7];
    const float mean = sum * (1.f / DD);
    const float var  = sq * (1.f / DD) - mean * mean;
    const float inv  = rsqrtf(var + EPS);
#pragma unroll
    for (int i = 0; i < 4; i++) {
        int c = tid + i * 128;
        out[(size_t)row * DD + c] = (v[i] - mean) * inv * s[c] + bta[c];
    }
}

// ---------------- mean pool (two-stage) -------------------------------------
__global__ void pool_partial(const float* __restrict__ emb, float* __restrict__ pp)
{
    const int b = blockIdx.x >> 5, ch = blockIdx.x & 31;
    const int d = threadIdx.x;
    float s = 0.f;
    const int t0 = ch * 64;
    for (int t = t0; t < t0 + 64; t++)
        s += emb[((size_t)(b * TT + t)) * DD + d];
    pp[(size_t)blockIdx.x * DD + d] = s;
}

__global__ void pool_reduce(const float* __restrict__ pp, float* __restrict__ p)
{
    const int b = blockIdx.x, d = threadIdx.x;
    float s = 0.f;
    for (int ch = 0; ch < 32; ch++)
        s += pp[(size_t)(b * 32 + ch) * DD + d];
    p[b * DD + d] = s * (1.f / TT);
}

// ---------------- tiny dense layer (heads) ----------------------------------
__global__ void small_linear(const float* __restrict__ in, const float* __restrict__ W,
                             const float* __restrict__ bias, float* __restrict__ out,
                             int K, int N, int relu)
{
    const int b = blockIdx.x, n = threadIdx.x;
    if (n >= N) return;
    float sum = bias[n];
    for (int k = 0; k < K; k++)
        sum = fmaf(in[b * K + k], W[(size_t)k * N + n], sum);
    if (relu) sum = fmaxf(sum, 0.f);
    out[b * N + n] = sum;
}

// ---------------- launch -----------------------------------------------------
extern "C" void kernel_launch(void* const* d_in, const int* in_sizes, int n_in,
                              void* d_out, int out_size)
{
    const float* feats  = (const float*)d_in[0];
    const float* projW  = (const float*)d_in[1];
    const float* projB  = (const float*)d_in[2];
    const float* posenc = (const float*)d_in[3];
    const float* qkvW   = (const float*)d_in[4];
    const float* qkvB   = (const float*)d_in[5];
    const float* outW   = (const float*)d_in[6];
    const float* outB   = (const float*)d_in[7];
    const float* ln1s   = (const float*)d_in[8];
    const float* ln1b   = (const float*)d_in[9];
    const float* ff1W   = (const float*)d_in[10];
    const float* ff1B   = (const float*)d_in[11];
    const float* ff2W   = (const float*)d_in[12];
    const float* ff2B   = (const float*)d_in[13];
    const float* ln2s   = (const float*)d_in[14];
    const float* ln2b   = (const float*)d_in[15];
    const float* mu1W   = (const float*)d_in[16];
    const float* mu1B   = (const float*)d_in[17];
    const float* mu2W   = (const float*)d_in[18];
    const float* mu2B   = (const float*)d_in[19];
    const float* lv1W   = (const float*)d_in[20];
    const float* lv1B   = (const float*)d_in[21];
    const float* lv2W   = (const float*)d_in[22];
    const float* lv2B   = (const float*)d_in[23];

    float *px, *pqkv, *pctx, *ptmp, *pff, *ppool, *ppp, *ph;
    cudaGetSymbolAddress((void**)&px,    g_x);
    cudaGetSymbolAddress((void**)&pqkv,  g_qkv);
    cudaGetSymbolAddress((void**)&pctx,  g_ctx);
    cudaGetSymbolAddress((void**)&ptmp,  g_tmp);
    cudaGetSymbolAddress((void**)&pff,   g_ff);
    cudaGetSymbolAddress((void**)&ppool, g_pool);
    cudaGetSymbolAddress((void**)&ppp,   g_pp);
    cudaGetSymbolAddress((void**)&ph,    g_h);

    cudaFuncSetAttribute(gemm_tf32<0>, cudaFuncAttributeMaxDynamicSharedMemorySize, GEMM_SMEM);
    cudaFuncSetAttribute(gemm_tf32<1>, cudaFuncAttributeMaxDynamicSharedMemorySize, GEMM_SMEM);
    cudaFuncSetAttribute(gemm_tf32<2>, cudaFuncAttributeMaxDynamicSharedMemorySize, GEMM_SMEM);
    cudaFuncSetAttribute(attn_mma,     cudaFuncAttributeMaxDynamicSharedMemorySize, ATTN_SMEM);

    float* emb = (float*)d_out;
    float* mu  = emb + (size_t)ROWS * DD;
    float* lv  = mu + BB * LAT;

    // x = feats @ projW + projB + posenc
    {
        dim3 grid(DD / 128, ROWS / 128);
        gemm_tf32<2><<<grid, 256, GEMM_SMEM>>>(feats, projW, projB, posenc, px, ROWS, DD, INF_);
    }

    for (int l = 0; l < LL; l++) {
        {
            dim3 grid((3 * DD) / 128, ROWS / 128);
            gemm_tf32<0><<<grid, 256, GEMM_SMEM>>>(px, qkvW + (size_t)l * DD * 3 * DD,
                                        qkvB + l * 3 * DD, nullptr, pqkv,
                                        ROWS, 3 * DD, DD);
        }
        attn_mma<<<BB * HH * 32, 128, ATTN_SMEM>>>(pqkv, pctx);
        {
            dim3 grid(DD / 128, ROWS / 128);
            gemm_tf32<0><<<grid, 256, GEMM_SMEM>>>(pctx, outW + (size_t)l * DD * DD,
                                        outB + l * DD, nullptr, ptmp, ROWS, DD, DD);
        }
        add_ln<<<ROWS, 128>>>(px, ptmp, ln1s + l * DD, ln1b + l * DD, px);
        {
            dim3 grid(FF_ / 128, ROWS / 128);
            gemm_tf32<1><<<grid, 256, GEMM_SMEM>>>(px, ff1W + (size_t)l * DD * FF_,
                                        ff1B + l * FF_, nullptr, pff, ROWS, FF_, DD);
        }
        {
            dim3 grid(DD / 128, ROWS / 128);
            gemm_tf32<0><<<grid, 256, GEMM_SMEM>>>(pff, ff2W + (size_t)l * FF_ * DD,
                                        ff2B + l * DD, nullptr, ptmp, ROWS, DD, FF_);
        }
        float* dst = (l == LL - 1) ? emb : px;
        add_ln<<<ROWS, 128>>>(px, ptmp, ln2s + l * DD, ln2b + l * DD, dst);
    }

    pool_partial<<<BB * 32, DD>>>(emb, ppp);
    pool_reduce<<<BB, DD>>>(ppp, ppool);
    small_linear<<<BB, 2 * LAT>>>(ppool, mu1W, mu1B, ph, DD, 2 * LAT, 1);
    small_linear<<<BB, LAT>>>(ph, mu2W, mu2B, mu, 2 * LAT, LAT, 0);
    small_linear<<<BB, 2 * LAT>>>(ppool, lv1W, lv1B, ph, DD, 2 * LAT, 1);
    small_linear<<<BB, LAT>>>(ph, lv2W, lv2B, lv, 2 * LAT, LAT, 0);
}

// round 5
// speedup vs baseline: 2.7167x; 1.0038x over previous
#include <cuda_runtime.h>
#include <math.h>
#include <stdint.h>

// Problem constants
#define BB 4
#define TT 2048
#define INF_ 64
#define DD 512
#define HH 8
#define DH 64
#define FF_ 2048
#define LL 4
#define LAT 128
#define PAST 40
#define FUT 120
#define ROWS (BB*TT)          // 8192
#define EPS 1e-5f

// ---------------- scratch (device globals; no allocation allowed) ----------
__device__ float g_x   [ROWS * DD];
__device__ float g_qkv [ROWS * 3 * DD];
__device__ float g_ctx [ROWS * DD];
__device__ float g_tmp [ROWS * DD];
__device__ float g_ff  [ROWS * FF_];
__device__ float g_pool[BB * DD];
__device__ float g_pp  [BB * 32 * DD];
__device__ float g_h   [BB * 2 * LAT];

// ---------------- helpers ---------------------------------------------------
__device__ __forceinline__ float f2tf(float x) {
    uint32_t u;
    asm("cvt.rna.tf32.f32 %0, %1;" : "=r"(u) : "f"(x));
    return __uint_as_float(u);
}
__device__ __forceinline__ uint32_t f2tfu(float x) {
    uint32_t u;
    asm("cvt.rna.tf32.f32 %0, %1;" : "=r"(u) : "f"(x));
    return u;
}
__device__ __forceinline__ uint32_t sptr(const void* p) {
    return (uint32_t)__cvta_generic_to_shared(p);
}
__device__ __forceinline__ void cpa16(uint32_t dst, const void* src) {
    asm volatile("cp.async.cg.shared.global [%0], [%1], 16;\n" :: "r"(dst), "l"(src));
}
#define CP_COMMIT() asm volatile("cp.async.commit_group;\n")
#define CP_WAIT(n)  asm volatile("cp.async.wait_group %0;\n" :: "n"(n))

#define MMA_TF32(d0,d1,d2,d3,a0,a1,a2,a3,b0,b1)                              \
    asm volatile("mma.sync.aligned.m16n8k8.row.col.f32.tf32.tf32.f32 "       \
        "{%0,%1,%2,%3},{%4,%5,%6,%7},{%8,%9},{%0,%1,%2,%3};"                 \
        : "+f"(d0),"+f"(d1),"+f"(d2),"+f"(d3)                                \
        : "r"(a0),"r"(a1),"r"(a2),"r"(a3),"r"(b0),"r"(b1))

// ---------------- TF32 tensor-core GEMM, 3-stage cp.async pipeline ----------
// EPI: 0 = +bias ; 1 = +bias, relu ; 2 = +bias + pos_enc[row%T]
#define GEMM_APAD 20
#define GEMM_BPAD 136
#define GEMM_ASZ  (128 * GEMM_APAD)
#define GEMM_BSZ  (16 * GEMM_BPAD)
#define GEMM_SMEM (3 * (GEMM_ASZ + GEMM_BSZ) * 4)   // 56832 B

template <int EPI>
__global__ __launch_bounds__(256)
void gemm_tf32(const float* __restrict__ A, const float* __restrict__ B,
               const float* __restrict__ bias, const float* __restrict__ extra,
               float* __restrict__ C, int M, int N, int K)
{
    constexpr int BM = 128, BN = 128, BK = 16;
    extern __shared__ float sm[];
    float* As = sm;
    float* Bs = sm + 3 * GEMM_ASZ;

    const int tid  = threadIdx.x;
    const int wid  = tid >> 5, lane = tid & 31;
    const int g    = lane >> 2, c = lane & 3;
    const int wm   = (wid >> 2) * 64;
    const int wn   = (wid & 3) * 32;
    const int brow = blockIdx.y * BM, bcol = blockIdx.x * BN;

    const int arow = tid >> 1,  acol = (tid & 1) * 8;
    const int brw  = tid >> 4,  bcl  = (tid & 15) * 8;

    const float* Ag = A + (size_t)(brow + arow) * K + acol;
    const float* Bg = B + bcol + bcl;

    const uint32_t sA = sptr(As) + (uint32_t)(arow * GEMM_APAD + acol) * 4u;
    const uint32_t sB = sptr(Bs) + (uint32_t)(brw * GEMM_BPAD + bcl) * 4u;

    float acc[4][4][4];
#pragma unroll
    for (int i = 0; i < 4; i++)
#pragma unroll
        for (int j = 0; j < 4; j++)
#pragma unroll
            for (int r = 0; r < 4; r++) acc[i][j][r] = 0.f;

    const int nk = K / BK;

    {
        cpa16(sA, Ag);       cpa16(sA + 16, Ag + 4);
        cpa16(sB, Bg + (size_t)brw * N);
        cpa16(sB + 16, Bg + (size_t)brw * N + 4);
        CP_COMMIT();
        if (nk > 1) {
            cpa16(sA + GEMM_ASZ * 4, Ag + BK);
            cpa16(sA + GEMM_ASZ * 4 + 16, Ag + BK + 4);
            cpa16(sB + GEMM_BSZ * 4, Bg + (size_t)(BK + brw) * N);
            cpa16(sB + GEMM_BSZ * 4 + 16, Bg + (size_t)(BK + brw) * N + 4);
            CP_COMMIT();
            CP_WAIT(1);
        } else {
            CP_WAIT(0);
        }
        __syncthreads();
    }

    int s_cur = 0;
    for (int k0 = 0; k0 < nk; k0++) {
        if (k0 + 2 < nk) {
            const int s = (s_cur + 2 >= 3) ? s_cur - 1 : s_cur + 2;
            const float* ga = Ag + (k0 + 2) * BK;
            cpa16(sA + s * GEMM_ASZ * 4, ga);
            cpa16(sA + s * GEMM_ASZ * 4 + 16, ga + 4);
            const float* gb = Bg + (size_t)((k0 + 2) * BK + brw) * N;
            cpa16(sB + s * GEMM_BSZ * 4, gb);
            cpa16(sB + s * GEMM_BSZ * 4 + 16, gb + 4);
            CP_COMMIT();
        }

        const float* Ab = As + s_cur * GEMM_ASZ;
        const float* Bb = Bs + s_cur * GEMM_BSZ;
#pragma unroll
        for (int kk = 0; kk < 2; kk++) {
            uint32_t af[4][4];
#pragma unroll
            for (int mt = 0; mt < 4; mt++) {
                const int m0 = wm + mt * 16 + g;
                af[mt][0] = f2tfu(Ab[(m0    ) * GEMM_APAD + kk * 8 + c    ]);
                af[mt][1] = f2tfu(Ab[(m0 + 8) * GEMM_APAD + kk * 8 + c    ]);
                af[mt][2] = f2tfu(Ab[(m0    ) * GEMM_APAD + kk * 8 + c + 4]);
                af[mt][3] = f2tfu(Ab[(m0 + 8) * GEMM_APAD + kk * 8 + c + 4]);
            }
            uint32_t bf[4][2];
#pragma unroll
            for (int nt = 0; nt < 4; nt++) {
                const int n0 = wn + nt * 8 + g;
                bf[nt][0] = f2tfu(Bb[(kk * 8 + c    ) * GEMM_BPAD + n0]);
                bf[nt][1] = f2tfu(Bb[(kk * 8 + c + 4) * GEMM_BPAD + n0]);
            }
#pragma unroll
            for (int mt = 0; mt < 4; mt++)
#pragma unroll
                for (int nt = 0; nt < 4; nt++)
                    MMA_TF32(acc[mt][nt][0], acc[mt][nt][1], acc[mt][nt][2], acc[mt][nt][3],
                             af[mt][0], af[mt][1], af[mt][2], af[mt][3],
                             bf[nt][0], bf[nt][1]);
        }

        if (k0 + 1 < nk) {
            if (k0 + 2 < nk) CP_WAIT(1); else CP_WAIT(0);
            __syncthreads();
        }
        s_cur = (s_cur + 1 >= 3) ? 0 : s_cur + 1;
    }

#pragma unroll
    for (int mt = 0; mt < 4; mt++) {
#pragma unroll
        for (int nt = 0; nt < 4; nt++) {
            const int col = bcol + wn + nt * 8 + 2 * c;
            const float b0 = bias[col], b1 = bias[col + 1];
#pragma unroll
            for (int half = 0; half < 2; half++) {
                const int row = brow + wm + mt * 16 + g + half * 8;
                float v0 = acc[mt][nt][half * 2 + 0] + b0;
                float v1 = acc[mt][nt][half * 2 + 1] + b1;
                if (EPI == 1) { v0 = fmaxf(v0, 0.f); v1 = fmaxf(v1, 0.f); }
                if (EPI == 2) {
                    const int t = row & (TT - 1);
                    v0 += extra[(size_t)t * N + col];
                    v1 += extra[(size_t)t * N + col + 1];
                }
                float2 o; o.x = v0; o.y = v1;
                *(float2*)(C + (size_t)row * N + col) = o;
            }
        }
    }
}

// ---------------- banded flash attention v2 ---------------------------------
// Block: 128 queries of one (b,h). 8 warps, 16 query rows each.
// Key window: up to 5 aligned 64-key chunks {q0-64, q0, q0+64, q0+128, q0+192}.
// P never touches smem: PV A-fragments built from softmax accumulators via shfl.
// Per-warp fully-masked key-group skipping.
#define KVP 72
#define ABUF (64 * KVP)
#define ATTN_SMEM (4 * ABUF * 4)   // Ks[2] + Vs[2] = 73728 B

__global__ __launch_bounds__(256, 2)
void attn_mma(const float* __restrict__ qkv, float* __restrict__ ctx)
{
    extern __shared__ float sm[];
    float* Ks = sm;                 // [2][64][72]
    float* Vs = sm + 2 * ABUF;      // [2][64][72]

    const int blk = blockIdx.x;
    const int qt = blk & 15;
    const int h  = (blk >> 4) & 7;
    const int b  = blk >> 7;
    const int q0 = qt * 128;

    const int tid = threadIdx.x, wid = tid >> 5, lane = tid & 31;
    const int g = lane >> 2, c = lane & 3;
    const int w0 = q0 + wid * 16;            // warp's first query row
    const int r0 = w0 + g, r1 = r0 + 8;

    // ---- Q fragments (tf32)
    uint32_t qa[8][4];
#pragma unroll
    for (int kt = 0; kt < 8; kt++) {
        const float* q_lo = qkv + (size_t)(b * TT + r0) * 1536 + h * 64 + kt * 8;
        const float* q_hi = qkv + (size_t)(b * TT + r1) * 1536 + h * 64 + kt * 8;
        qa[kt][0] = f2tfu(q_lo[c]);
        qa[kt][1] = f2tfu(q_hi[c]);
        qa[kt][2] = f2tfu(q_lo[c + 4]);
        qa[kt][3] = f2tfu(q_hi[c + 4]);
    }

    float oacc[8][4];
#pragma unroll
    for (int nt = 0; nt < 8; nt++)
#pragma unroll
        for (int e = 0; e < 4; e++) oacc[nt][e] = 0.f;

    float m0 = -INFINITY, m1 = -INFINITY, l0 = 0.f, l1 = 0.f;
    const float scale = 0.125f;

    // chunk list (any order is numerically safe via fmax guards)
    int csv[5]; int ncs = 0;
    const int offs[5] = {-64, 0, 64, 128, 192};
#pragma unroll
    for (int i = 0; i < 5; i++) {
        const int cs = q0 + offs[i];
        if (cs >= 0 && cs < TT) csv[ncs++] = cs;
    }

    // loader: 256 threads; tid>>7 selects K/V, row = (tid>>1)&63, half = tid&1
    const int lrow  = (tid >> 1) & 63;
    const int isv   = tid >> 7;
    const int lhalf = tid & 1;
    const uint32_t ldst0 = sptr((isv ? Vs : Ks) + lrow * KVP + lhalf * 32);
    const size_t lsrc_off = (size_t)512 + (size_t)isv * 512 + h * 64 + lhalf * 32;

    {   // prologue: chunk 0
        const float* src = qkv + (size_t)(b * TT + csv[0] + lrow) * 1536 + lsrc_off;
#pragma unroll
        for (int i = 0; i < 8; i++) cpa16(ldst0 + i * 16, src + i * 4);
        CP_COMMIT();
    }

    // PV shuffle sources (constant per thread)
    const int srcA = (lane & 28) | (c >> 1);
    const int srcB = srcA + 2;
    const bool odd = (c & 1) != 0;

    for (int ci = 0; ci < ncs; ci++) {
        CP_WAIT(0);
        __syncthreads();

        if (ci + 1 < ncs) {
            const uint32_t dst = ldst0 + ((ci + 1) & 1) * ABUF * 4;
            const float* src = qkv + (size_t)(b * TT + csv[ci + 1] + lrow) * 1536 + lsrc_off;
#pragma unroll
            for (int i = 0; i < 8; i++) cpa16(dst + i * 16, src + i * 4);
            CP_COMMIT();
        }

        const int cs = csv[ci];
        // warp-valid key-group range within this chunk
        const int lo_key = max(cs, w0 - PAST);
        const int hi_key = min(cs + 63, w0 + 15 + FUT);
        if (lo_key > hi_key) continue;        // warp-uniform; next iter syncs
        const int ntlo = (lo_key - cs) >> 3;
        const int nthi = (hi_key - cs) >> 3;

        const float* Kb = Ks + (ci & 1) * ABUF;
        const float* Vb = Vs + (ci & 1) * ABUF;

        // ---- S = Q @ K^T for valid groups
        float sacc[8][4];
#pragma unroll
        for (int nt = 0; nt < 8; nt++) {
            sacc[nt][0] = 0.f; sacc[nt][1] = 0.f;
            sacc[nt][2] = 0.f; sacc[nt][3] = 0.f;
        }
#pragma unroll
        for (int nt = 0; nt < 8; nt++) {
            if (nt < ntlo || nt > nthi) continue;
#pragma unroll
            for (int kt = 0; kt < 8; kt++) {
                const uint32_t b0 = f2tfu(Kb[(nt * 8 + g) * KVP + kt * 8 + c]);
                const uint32_t b1 = f2tfu(Kb[(nt * 8 + g) * KVP + kt * 8 + c + 4]);
                MMA_TF32(sacc[nt][0], sacc[nt][1], sacc[nt][2], sacc[nt][3],
                         qa[kt][0], qa[kt][1], qa[kt][2], qa[kt][3], b0, b1);
            }
        }

        // ---- mask + row max over valid groups
        float mx0 = -INFINITY, mx1 = -INFINITY;
#pragma unroll
        for (int nt = 0; nt < 8; nt++) {
            if (nt < ntlo || nt > nthi) continue;
            const int j0 = cs + nt * 8 + 2 * c;
            const int j1 = j0 + 1;
            float v;
            v = sacc[nt][0] * scale;
            v = (j0 >= r0 - PAST && j0 <= r0 + FUT) ? v : -INFINITY;
            sacc[nt][0] = v; mx0 = fmaxf(mx0, v);
            v = sacc[nt][1] * scale;
            v = (j1 >= r0 - PAST && j1 <= r0 + FUT) ? v : -INFINITY;
            sacc[nt][1] = v; mx0 = fmaxf(mx0, v);
            v = sacc[nt][2] * scale;
            v = (j0 >= r1 - PAST && j0 <= r1 + FUT) ? v : -INFINITY;
            sacc[nt][2] = v; mx1 = fmaxf(mx1, v);
            v = sacc[nt][3] * scale;
            v = (j1 >= r1 - PAST && j1 <= r1 + FUT) ? v : -INFINITY;
            sacc[nt][3] = v; mx1 = fmaxf(mx1, v);
        }
        mx0 = fmaxf(mx0, __shfl_xor_sync(0xffffffffu, mx0, 1));
        mx0 = fmaxf(mx0, __shfl_xor_sync(0xffffffffu, mx0, 2));
        mx1 = fmaxf(mx1, __shfl_xor_sync(0xffffffffu, mx1, 1));
        mx1 = fmaxf(mx1, __shfl_xor_sync(0xffffffffu, mx1, 2));

        const float mn0 = fmaxf(m0, mx0);
        const float mn1 = fmaxf(m1, mx1);
        // fmax guard: (-inf) - (-inf) = nan -> fmaxf(nan, -88) = -88 -> exp ~ 0
        const float rf0 = __expf(fmaxf(m0 - mn0, -88.f));
        const float rf1 = __expf(fmaxf(m1 - mn1, -88.f));
        m0 = mn0; m1 = mn1;

        // ---- p = exp(s - m) in place (tf32-rounded), row sums
        float ps0 = 0.f, ps1 = 0.f;
#pragma unroll
        for (int nt = 0; nt < 8; nt++) {
            if (nt < ntlo || nt > nthi) continue;
            const float p00 = __expf(fmaxf(sacc[nt][0] - mn0, -88.f));
            const float p01 = __expf(fmaxf(sacc[nt][1] - mn0, -88.f));
            const float p10 = __expf(fmaxf(sacc[nt][2] - mn1, -88.f));
            const float p11 = __expf(fmaxf(sacc[nt][3] - mn1, -88.f));
            ps0 += p00 + p01;
            ps1 += p10 + p11;
            sacc[nt][0] = f2tf(p00);
            sacc[nt][1] = f2tf(p01);
            sacc[nt][2] = f2tf(p10);
            sacc[nt][3] = f2tf(p11);
        }
        ps0 += __shfl_xor_sync(0xffffffffu, ps0, 1);
        ps0 += __shfl_xor_sync(0xffffffffu, ps0, 2);
        ps1 += __shfl_xor_sync(0xffffffffu, ps1, 1);
        ps1 += __shfl_xor_sync(0xffffffffu, ps1, 2);
        l0 = l0 * rf0 + ps0;
        l1 = l1 * rf1 + ps1;

#pragma unroll
        for (int nt = 0; nt < 8; nt++) {
            oacc[nt][0] *= rf0; oacc[nt][1] *= rf0;
            oacc[nt][2] *= rf1; oacc[nt][3] *= rf1;
        }

        // ---- O += P @ V ; A-fragments built via shuffle from sacc
#pragma unroll
        for (int kt = 0; kt < 8; kt++) {
            if (kt < ntlo || kt > nthi) continue;
            float v00 = __shfl_sync(0xffffffffu, sacc[kt][0], srcA);
            float v01 = __shfl_sync(0xffffffffu, sacc[kt][1], srcA);
            float v10 = __shfl_sync(0xffffffffu, sacc[kt][2], srcA);
            float v11 = __shfl_sync(0xffffffffu, sacc[kt][3], srcA);
            const uint32_t a0 = __float_as_uint(odd ? v01 : v00);
            const uint32_t a1 = __float_as_uint(odd ? v11 : v10);
            v00 = __shfl_sync(0xffffffffu, sacc[kt][0], srcB);
            v01 = __shfl_sync(0xffffffffu, sacc[kt][1], srcB);
            v10 = __shfl_sync(0xffffffffu, sacc[kt][2], srcB);
            v11 = __shfl_sync(0xffffffffu, sacc[kt][3], srcB);
            const uint32_t a2 = __float_as_uint(odd ? v01 : v00);
            const uint32_t a3 = __float_as_uint(odd ? v11 : v10);
#pragma unroll
            for (int nt = 0; nt < 8; nt++) {
                const uint32_t b0 = f2tfu(Vb[(kt * 8 + c    ) * KVP + nt * 8 + g]);
                const uint32_t b1 = f2tfu(Vb[(kt * 8 + c + 4) * KVP + nt * 8 + g]);
                MMA_TF32(oacc[nt][0], oacc[nt][1], oacc[nt][2], oacc[nt][3],
                         a0, a1, a2, a3, b0, b1);
            }
        }
    }

    // ---- write O
    const float inv0 = 1.f / l0, inv1 = 1.f / l1;
#pragma unroll
    for (int nt = 0; nt < 8; nt++) {
        const int col = h * 64 + nt * 8 + 2 * c;
        float2 w;
        w.x = oacc[nt][0] * inv0; w.y = oacc[nt][1] * inv0;
        *(float2*)(ctx + (size_t)(b * TT + r0) * DD + col) = w;
        w.x = oacc[nt][2] * inv1; w.y = oacc[nt][3] * inv1;
        *(float2*)(ctx + (size_t)(b * TT + r1) * DD + col) = w;
    }
}

// ---------------- residual add + LayerNorm (row = 512) ---------------------
__global__ __launch_bounds__(128)
void add_ln(const float* __restrict__ x, const float* __restrict__ y,
            const float* __restrict__ s, const float* __restrict__ bta,
            float* __restrict__ out)
{
    const int row = blockIdx.x;
    const int tid = threadIdx.x;
    float v[4];
    float sum = 0.f, sq = 0.f;
#pragma unroll
    for (int i = 0; i < 4; i++) {
        int c = tid + i * 128;
        float val = x[(size_t)row * DD + c] + y[(size_t)row * DD + c];
        v[i] = val;
        sum += val;
        sq  += val * val;
    }
    __shared__ float rs[8];
#pragma unroll
    for (int off = 16; off > 0; off >>= 1) {
        sum += __shfl_xor_sync(0xffffffffu, sum, off);
        sq  += __shfl_xor_sync(0xffffffffu, sq,  off);
    }
    if ((tid & 31) == 0) { rs[tid >> 5] = sum; rs[4 + (tid >> 5)] = sq; }
    __syncthreads();
    sum = rs[0] + rs[1] + rs[2] + rs[3];
    sq  = rs[4] + rs[5] + rs[6] + rs[7];
    const float mean = sum * (1.f / DD);
    const float var  = sq * (1.f / DD) - mean * mean;
    const float inv  = rsqrtf(var + EPS);
#pragma unroll
    for (int i = 0; i < 4; i++) {
        int c = tid + i * 128;
        out[(size_t)row * DD + c] = (v[i] - mean) * inv * s[c] + bta[c];
    }
}

// ---------------- mean pool (two-stage) -------------------------------------
__global__ void pool_partial(const float* __restrict__ emb, float* __restrict__ pp)
{
    const int b = blockIdx.x >> 5, ch = blockIdx.x & 31;
    const int d = threadIdx.x;
    float s = 0.f;
    const int t0 = ch * 64;
    for (int t = t0; t < t0 + 64; t++)
        s += emb[((size_t)(b * TT + t)) * DD + d];
    pp[(size_t)blockIdx.x * DD + d] = s;
}

__global__ void pool_reduce(const float* __restrict__ pp, float* __restrict__ p)
{
    const int b = blockIdx.x, d = threadIdx.x;
    float s = 0.f;
    for (int ch = 0; ch < 32; ch++)
        s += pp[(size_t)(b * 32 + ch) * DD + d];
    p[b * DD + d] = s * (1.f / TT);
}

// ---------------- tiny dense layer (heads) ----------------------------------
__global__ void small_linear(const float* __restrict__ in, const float* __restrict__ W,
                             const float* __restrict__ bias, float* __restrict__ out,
                             int K, int N, int relu)
{
    const int b = blockIdx.x, n = threadIdx.x;
    if (n >= N) return;
    float sum = bias[n];
    for (int k = 0; k < K; k++)
        sum = fmaf(in[b * K + k], W[(size_t)k * N + n], sum);
    if (relu) sum = fmaxf(sum, 0.f);
    out[b * N + n] = sum;
}

// ---------------- launch -----------------------------------------------------
extern "C" void kernel_launch(void* const* d_in, const int* in_sizes, int n_in,
                              void* d_out, int out_size)
{
    const float* feats  = (const float*)d_in[0];
    const float* projW  = (const float*)d_in[1];
    const float* projB  = (const float*)d_in[2];
    const float* posenc = (const float*)d_in[3];
    const float* qkvW   = (const float*)d_in[4];
    const float* qkvB   = (const float*)d_in[5];
    const float* outW   = (const float*)d_in[6];
    const float* outB   = (const float*)d_in[7];
    const float* ln1s   = (const float*)d_in[8];
    const float* ln1b   = (const float*)d_in[9];
    const float* ff1W   = (const float*)d_in[10];
    const float* ff1B   = (const float*)d_in[11];
    const float* ff2W   = (const float*)d_in[12];
    const float* ff2B   = (const float*)d_in[13];
    const float* ln2s   = (const float*)d_in[14];
    const float* ln2b   = (const float*)d_in[15];
    const float* mu1W   = (const float*)d_in[16];
    const float* mu1B   = (const float*)d_in[17];
    const float* mu2W   = (const float*)d_in[18];
    const float* mu2B   = (const float*)d_in[19];
    const float* lv1W   = (const float*)d_in[20];
    const float* lv1B   = (const float*)d_in[21];
    const float* lv2W   = (const float*)d_in[22];
    const float* lv2B   = (const float*)d_in[23];

    float *px, *pqkv, *pctx, *ptmp, *pff, *ppool, *ppp, *ph;
    cudaGetSymbolAddress((void**)&px,    g_x);
    cudaGetSymbolAddress((void**)&pqkv,  g_qkv);
    cudaGetSymbolAddress((void**)&pctx,  g_ctx);
    cudaGetSymbolAddress((void**)&ptmp,  g_tmp);
    cudaGetSymbolAddress((void**)&pff,   g_ff);
    cudaGetSymbolAddress((void**)&ppool, g_pool);
    cudaGetSymbolAddress((void**)&ppp,   g_pp);
    cudaGetSymbolAddress((void**)&ph,    g_h);

    cudaFuncSetAttribute(gemm_tf32<0>, cudaFuncAttributeMaxDynamicSharedMemorySize, GEMM_SMEM);
    cudaFuncSetAttribute(gemm_tf32<1>, cudaFuncAttributeMaxDynamicSharedMemorySize, GEMM_SMEM);
    cudaFuncSetAttribute(gemm_tf32<2>, cudaFuncAttributeMaxDynamicSharedMemorySize, GEMM_SMEM);
    cudaFuncSetAttribute(attn_mma,     cudaFuncAttributeMaxDynamicSharedMemorySize, ATTN_SMEM);

    float* emb = (float*)d_out;
    float* mu  = emb + (size_t)ROWS * DD;
    float* lv  = mu + BB * LAT;

    // x = feats @ projW + projB + posenc
    {
        dim3 grid(DD / 128, ROWS / 128);
        gemm_tf32<2><<<grid, 256, GEMM_SMEM>>>(feats, projW, projB, posenc, px, ROWS, DD, INF_);
    }

    for (int l = 0; l < LL; l++) {
        {
            dim3 grid((3 * DD) / 128, ROWS / 128);
            gemm_tf32<0><<<grid, 256, GEMM_SMEM>>>(px, qkvW + (size_t)l * DD * 3 * DD,
                                        qkvB + l * 3 * DD, nullptr, pqkv,
                                        ROWS, 3 * DD, DD);
        }
        attn_mma<<<BB * HH * 16, 256, ATTN_SMEM>>>(pqkv, pctx);
        {
            dim3 grid(DD / 128, ROWS / 128);
            gemm_tf32<0><<<grid, 256, GEMM_SMEM>>>(pctx, outW + (size_t)l * DD * DD,
                                        outB + l * DD, nullptr, ptmp, ROWS, DD, DD);
        }
        add_ln<<<ROWS, 128>>>(px, ptmp, ln1s + l * DD, ln1b + l * DD, px);
        {
            dim3 grid(FF_ / 128, ROWS / 128);
            gemm_tf32<1><<<grid, 256, GEMM_SMEM>>>(px, ff1W + (size_t)l * DD * FF_,
                                        ff1B + l * FF_, nullptr, pff, ROWS, FF_, DD);
        }
        {
            dim3 grid(DD / 128, ROWS / 128);
            gemm_tf32<0><<<grid, 256, GEMM_SMEM>>>(pff, ff2W + (size_t)l * FF_ * DD,
                                        ff2B + l * DD, nullptr, ptmp, ROWS, DD, FF_);
        }
        float* dst = (l == LL - 1) ? emb : px;
        add_ln<<<ROWS, 128>>>(px, ptmp, ln2s + l * DD, ln2b + l * DD, dst);
    }

    pool_partial<<<BB * 32, DD>>>(emb, ppp);
    pool_reduce<<<BB, DD>>>(ppp, ppool);
    small_linear<<<BB, 2 * LAT>>>(ppool, mu1W, mu1B, ph, DD, 2 * LAT, 1);
    small_linear<<<BB, LAT>>>(ph, mu2W, mu2B, mu, 2 * LAT, LAT, 0);
    small_linear<<<BB, 2 * LAT>>>(ppool, lv1W, lv1B, ph, DD, 2 * LAT, 1);
    small_linear<<<BB, LAT>>>(ph, lv2W, lv2B, lv, 2 * LAT, LAT, 0);
}